// round 9
// baseline (speedup 1.0000x reference)
#include <cuda_runtime.h>
#include <cuda_bf16.h>
#include <cuda_fp16.h>
#include <cstdint>

#define BATCH   2
#define SEQ     2048
#define EMBED   1024
#define HEADS   16
#define HDIM    64
#define FFN_DIM 4096
#define TOKENS  (BATCH * SEQ)

// ---------------- scratch (no allocations allowed) ----------------
__device__ float g_H [TOKENS * EMBED];
__device__ float g_X1[TOKENS * EMBED];
__device__ float g_T [TOKENS * EMBED];
__device__ float g_Q [TOKENS * EMBED];   // layout [n][h][s][d]
__device__ float g_K [TOKENS * EMBED];
__device__ float g_V [TOKENS * EMBED];
__device__ uint16_t g_Oh [TOKENS * EMBED];    // attention out, fp16
__device__ uint16_t g_X1h[TOKENS * EMBED];    // LN1 out, fp16
__device__ uint16_t g_Fh [TOKENS * FFN_DIM];  // FFN mid, fp16

// pre-split fp16 hi/lo weight copies (per layer, contiguous)
__device__ uint16_t g_WoHi[3 * EMBED * EMBED];
__device__ uint16_t g_WoLo[3 * EMBED * EMBED];
__device__ uint16_t g_W1Hi[3 * EMBED * FFN_DIM];
__device__ uint16_t g_W1Lo[3 * EMBED * FFN_DIM];
__device__ uint16_t g_W2Hi[3 * FFN_DIM * EMBED];
__device__ uint16_t g_W2Lo[3 * FFN_DIM * EMBED];

// ---------------- common helpers ----------------
__device__ __forceinline__ uint32_t pack_bf16(float x, float y) {
    __nv_bfloat162 h = __floats2bfloat162_rn(x, y);
    return *reinterpret_cast<uint32_t*>(&h);
}
__device__ __forceinline__ uint32_t pack_f16(float x, float y) {
    __half2 h = __floats2half2_rn(x, y);
    return *reinterpret_cast<uint32_t*>(&h);
}

__device__ __forceinline__ void split2(float x, float y, uint32_t& hi, uint32_t& lo) {
    float hx = __bfloat162float(__float2bfloat16_rn(x));
    float hy = __bfloat162float(__float2bfloat16_rn(y));
    hi = pack_bf16(hx, hy);
    lo = pack_bf16(x - hx, y - hy);
}

__device__ __forceinline__ void split_store4(uint16_t* Hi, uint16_t* Lo, int off, float4 v) {
    float h0 = __bfloat162float(__float2bfloat16_rn(v.x));
    float h1 = __bfloat162float(__float2bfloat16_rn(v.y));
    float h2 = __bfloat162float(__float2bfloat16_rn(v.z));
    float h3 = __bfloat162float(__float2bfloat16_rn(v.w));
    *(uint32_t*)&Hi[off]     = pack_bf16(h0, h1);
    *(uint32_t*)&Hi[off + 2] = pack_bf16(h2, h3);
    *(uint32_t*)&Lo[off]     = pack_bf16(v.x - h0, v.y - h1);
    *(uint32_t*)&Lo[off + 2] = pack_bf16(v.z - h2, v.w - h3);
}

#define MMA_BF16(d, a, b0, b1)                                              \
    asm volatile(                                                           \
        "mma.sync.aligned.m16n8k16.row.col.f32.bf16.bf16.f32 "              \
        "{%0,%1,%2,%3}, {%4,%5,%6,%7}, {%8,%9}, {%0,%1,%2,%3};"             \
        : "+f"(d[0]), "+f"(d[1]), "+f"(d[2]), "+f"(d[3])                    \
        : "r"(a[0]), "r"(a[1]), "r"(a[2]), "r"(a[3]), "r"(b0), "r"(b1))

#define MMA_F16(d, a, b0, b1)                                               \
    asm volatile(                                                           \
        "mma.sync.aligned.m16n8k16.row.col.f32.f16.f16.f32 "                \
        "{%0,%1,%2,%3}, {%4,%5,%6,%7}, {%8,%9}, {%0,%1,%2,%3};"             \
        : "+f"(d[0]), "+f"(d[1]), "+f"(d[2]), "+f"(d[3])                    \
        : "r"(a[0]), "r"(a[1]), "r"(a[2]), "r"(a[3]), "r"(b0), "r"(b1))

#define LDSM_X4(r, addr)                                                    \
    asm volatile("ldmatrix.sync.aligned.m8n8.x4.shared.b16 {%0,%1,%2,%3}, [%4];" \
        : "=r"(r[0]), "=r"(r[1]), "=r"(r[2]), "=r"(r[3]) : "r"(addr))

#define LDSM_X4_T(r, addr)                                                  \
    asm volatile("ldmatrix.sync.aligned.m8n8.x4.trans.shared.b16 {%0,%1,%2,%3}, [%4];" \
        : "=r"(r[0]), "=r"(r[1]), "=r"(r[2]), "=r"(r[3]) : "r"(addr))

#define CP_ASYNC16(dst, src)                                                \
    asm volatile("cp.async.cg.shared.global [%0], [%1], 16;" :: "r"(dst), "l"(src))
#define CP_COMMIT  asm volatile("cp.async.commit_group;")
#define CP_WAIT0   asm volatile("cp.async.wait_group 0;")

// ---------------- weight pre-split: fp32 -> fp16 hi/lo ----------------
__global__ __launch_bounds__(256) void wsplit_f16_kernel(
    const float* __restrict__ src, uint16_t* __restrict__ hi,
    uint16_t* __restrict__ lo, int n4)
{
    int i = blockIdx.x * 256 + threadIdx.x;
    if (i >= n4) return;
    float4 v = ((const float4*)src)[i];
    float h0 = __half2float(__float2half_rn(v.x));
    float h1 = __half2float(__float2half_rn(v.y));
    float h2 = __half2float(__float2half_rn(v.z));
    float h3 = __half2float(__float2half_rn(v.w));
    ((uint2*)hi)[i] = make_uint2(pack_f16(h0, h1), pack_f16(h2, h3));
    ((uint2*)lo)[i] = make_uint2(pack_f16(v.x - h0, v.y - h1),
                                 pack_f16(v.z - h2, v.w - h3));
}

// ---------------- embed: H = x @ embed_W + embed_b + pe ----------------
__global__ __launch_bounds__(256) void embed_kernel(
    const float* __restrict__ X, const float* __restrict__ W,
    const float* __restrict__ b, const float* __restrict__ pe,
    float* __restrict__ H)
{
    int token = blockIdx.x;
    int s = token % SEQ;
    __shared__ float xs[64];
    int tid = threadIdx.x;
    if (tid < 64) xs[tid] = X[(size_t)token * 64 + tid];
    __syncthreads();
    #pragma unroll
    for (int j = 0; j < 4; j++) {
        int e = tid + j * 256;
        float acc = b[e] + pe[(size_t)s * EMBED + e];
        #pragma unroll 8
        for (int d = 0; d < 64; d++)
            acc += xs[d] * W[(size_t)d * EMBED + e];
        H[(size_t)token * EMBED + e] = acc;
    }
}

// ======== tensor-core QKV: [tokens*heads, 64] x [64, 64] GEMM x3 =========
#define QSTR 72
#define QKV_W_OFF    (2 * 128 * QSTR)
#define QKV_SMEM_BYTES ((2 * 128 * QSTR + 6 * 64 * QSTR) * 2)

__global__ __launch_bounds__(256) void qkv_tc_kernel(
    const float* __restrict__ H,
    const float* __restrict__ Wq, const float* __restrict__ Wk,
    const float* __restrict__ Wv,
    float* __restrict__ Q, float* __restrict__ K, float* __restrict__ V)
{
    extern __shared__ __align__(16) uint16_t qsm[];
    uint16_t* Ahi = qsm;
    uint16_t* Alo = qsm + 128 * QSTR;
    uint16_t* Wb  = qsm + QKV_W_OFF;

    const int tid = threadIdx.x, lane = tid & 31, w = tid >> 5;
    const int t0 = blockIdx.x * 8;

    #pragma unroll
    for (int i = 0; i < 8; i++) {
        int idx = i * 256 + tid;
        int row = idx >> 4, c4 = (idx & 15) * 4;
        float4 v = *(const float4*)&H[(size_t)(t0 + (row >> 4)) * EMBED
                                      + (row & 15) * 64 + c4];
        split_store4(Ahi, Alo, row * QSTR + c4, v);
    }
    #pragma unroll
    for (int i = 0; i < 12; i++) {
        int idx = i * 256 + tid;
        int which = idx >> 10;
        int rem = idx & 1023;
        int row = rem >> 4, c4 = (rem & 15) * 4;
        const float* Wp = (which == 0) ? Wq : (which == 1) ? Wk : Wv;
        float4 v = *(const float4*)&Wp[row * 64 + c4];
        uint16_t* hi = Wb + which * 2 * 64 * QSTR;
        uint16_t* lo = hi + 64 * QSTR;
        split_store4(hi, lo, row * QSTR + c4, v);
    }
    __syncthreads();

    const uint32_t sA  = (uint32_t)__cvta_generic_to_shared(Ahi);
    const uint32_t sAl = (uint32_t)__cvta_generic_to_shared(Alo);
    const uint32_t sW  = (uint32_t)__cvta_generic_to_shared(Wb);

    uint32_t ah[4][4], al[4][4];
    {
        int arow = w * 16 + (lane & 15);
        int aoff = ((lane >> 4) & 1) * 8;
        #pragma unroll
        for (int c = 0; c < 4; c++) {
            uint32_t off = (uint32_t)(arow * QSTR + c * 16 + aoff) * 2;
            LDSM_X4(ah[c], sA + off);
            LDSM_X4(al[c], sAl + off);
        }
    }

    const int b_krow = lane & 15;
    const int b_coff = ((lane >> 4) & 1) * 8;

    const int gt = t0 + w;
    const int n = gt >> 11, s = gt & (SEQ - 1);
    const int ha = lane >> 2, hb = ha + 8;
    const int cbase = (lane & 3) * 2;

    float* outs[3] = {Q, K, V};
    #pragma unroll
    for (int mat = 0; mat < 3; mat++) {
        const uint32_t bh_base = sW + (uint32_t)(mat * 2 * 64 * QSTR) * 2;
        const uint32_t bl_base = bh_base + (uint32_t)(64 * QSTR) * 2;

        float acc[8][4];
        #pragma unroll
        for (int j = 0; j < 8; j++)
            #pragma unroll
            for (int c = 0; c < 4; c++) acc[j][c] = 0.f;

        #pragma unroll
        for (int c = 0; c < 4; c++) {
            #pragma unroll
            for (int j2 = 0; j2 < 4; j2++) {
                uint32_t bh[4], bl[4];
                uint32_t off = (uint32_t)((c * 16 + b_krow) * QSTR + j2 * 16 + b_coff) * 2;
                LDSM_X4_T(bh, bh_base + off);
                LDSM_X4_T(bl, bl_base + off);
                #pragma unroll
                for (int t = 0; t < 2; t++) {
                    int j = j2 * 2 + t;
                    MMA_BF16(acc[j], ah[c], bh[2*t], bh[2*t+1]);
                    MMA_BF16(acc[j], ah[c], bl[2*t], bl[2*t+1]);
                    MMA_BF16(acc[j], al[c], bh[2*t], bh[2*t+1]);
                }
            }
        }

        float* P = outs[mat];
        float* pa = P + (((size_t)(n * HEADS + ha) * SEQ + s)) * HDIM + cbase;
        float* pb = P + (((size_t)(n * HEADS + hb) * SEQ + s)) * HDIM + cbase;
        #pragma unroll
        for (int j = 0; j < 8; j++) {
            *(float2*)&pa[j * 8] = make_float2(acc[j][0], acc[j][1]);
            *(float2*)&pb[j * 8] = make_float2(acc[j][2], acc[j][3]);
        }
    }
}

// ====== tensor-core flash attention (bf16 split); O written as fp16 ======
#define ASTR 72
__global__ __launch_bounds__(256, 1) void attn_tc_kernel(
    const float* __restrict__ Q, const float* __restrict__ K,
    const float* __restrict__ V, uint16_t* __restrict__ Oh)
{
    __shared__ __align__(16) uint16_t sm[2 * 128 * ASTR];
    uint16_t* Qhi = sm;
    uint16_t* Qlo = sm + 128 * ASTR;
    uint16_t* Khi = sm;
    uint16_t* Klo = sm + 64 * ASTR;
    uint16_t* Vhi = sm + 128 * ASTR;
    uint16_t* Vlo = sm + 192 * ASTR;

    const int tid = threadIdx.x, lane = tid & 31, w = tid >> 5;
    const int nh = blockIdx.y;
    const int n = nh >> 4, h = nh & 15;
    const int q0blk = blockIdx.x * 128;

    const float* Qg = Q + ((size_t)nh * SEQ + q0blk) * HDIM;
    const float* Kg = K + (size_t)nh * SEQ * HDIM;
    const float* Vg = V + (size_t)nh * SEQ * HDIM;

    float4 pk[4], pv[4];
    #pragma unroll
    for (int i = 0; i < 4; i++) {
        int idx = i * 256 + tid, r = idx >> 4, c4 = (idx & 15) * 4;
        pk[i] = *(const float4*)&Kg[(size_t)r * 64 + c4];
        pv[i] = *(const float4*)&Vg[(size_t)r * 64 + c4];
    }

    #pragma unroll
    for (int i = 0; i < 8; i++) {
        int idx = i * 256 + tid, r = idx >> 4, c = (idx & 15) * 4;
        float4 v = *(const float4*)&Qg[(size_t)r * 64 + c];
        v.x *= 0.03125f; v.y *= 0.03125f; v.z *= 0.03125f; v.w *= 0.03125f;
        split_store4(Qhi, Qlo, r * ASTR + c, v);
    }
    __syncthreads();

    uint32_t sQhi = (uint32_t)__cvta_generic_to_shared(Qhi);
    uint32_t sQlo = (uint32_t)__cvta_generic_to_shared(Qlo);
    uint32_t sKhi = (uint32_t)__cvta_generic_to_shared(Khi);
    uint32_t sKlo = (uint32_t)__cvta_generic_to_shared(Klo);
    uint32_t sVhi = (uint32_t)__cvta_generic_to_shared(Vhi);
    uint32_t sVlo = (uint32_t)__cvta_generic_to_shared(Vlo);

    uint32_t aqh[4][4], aql[4][4];
    {
        int arow = w * 16 + (lane & 15);
        int aoff = ((lane >> 4) & 1) * 8;
        #pragma unroll
        for (int c = 0; c < 4; c++) {
            uint32_t off = (uint32_t)(arow * ASTR + c * 16 + aoff) * 2;
            LDSM_X4(aqh[c], sQhi + off);
            LDSM_X4(aql[c], sQlo + off);
        }
    }
    __syncthreads();

    float o[8][4];
    #pragma unroll
    for (int j = 0; j < 8; j++)
        #pragma unroll
        for (int c = 0; c < 4; c++) o[j][c] = 0.f;
    float m0 = -1e30f, m1 = -1e30f, l0 = 0.f, l1 = 0.f;

    const int kb_row = lane & 15;
    const int kb_col = ((lane >> 4) & 1) * 8;
    const int vb_row = lane & 15;
    const int vb_col = ((lane >> 4) & 1) * 8;

    for (int kb = 0; kb < SEQ / 64; kb++) {
        #pragma unroll
        for (int i = 0; i < 4; i++) {
            int idx = i * 256 + tid, r = idx >> 4, c = (idx & 15) * 4;
            split_store4(Khi, Klo, r * ASTR + c, pk[i]);
            split_store4(Vhi, Vlo, r * ASTR + c, pv[i]);
        }
        __syncthreads();

        if (kb + 1 < SEQ / 64) {
            const float* kg = Kg + (size_t)(kb + 1) * 64 * 64;
            const float* vg = Vg + (size_t)(kb + 1) * 64 * 64;
            #pragma unroll
            for (int i = 0; i < 4; i++) {
                int idx = i * 256 + tid, r = idx >> 4, c4 = (idx & 15) * 4;
                pk[i] = *(const float4*)&kg[(size_t)r * 64 + c4];
                pv[i] = *(const float4*)&vg[(size_t)r * 64 + c4];
            }
        }

        float s[8][4];
        #pragma unroll
        for (int j = 0; j < 8; j++)
            #pragma unroll
            for (int c = 0; c < 4; c++) s[j][c] = 0.f;

        #pragma unroll
        for (int c = 0; c < 4; c++) {
            #pragma unroll
            for (int j2 = 0; j2 < 4; j2++) {
                uint32_t kh[4], kl[4];
                uint32_t off = (uint32_t)((j2 * 16 + kb_row) * ASTR + c * 16 + kb_col) * 2;
                LDSM_X4(kh, sKhi + off);
                LDSM_X4(kl, sKlo + off);
                MMA_BF16(s[2*j2],   aqh[c], kh[0], kh[2]);
                MMA_BF16(s[2*j2],   aqh[c], kl[0], kl[2]);
                MMA_BF16(s[2*j2],   aql[c], kh[0], kh[2]);
                MMA_BF16(s[2*j2+1], aqh[c], kh[1], kh[3]);
                MMA_BF16(s[2*j2+1], aqh[c], kl[1], kl[3]);
                MMA_BF16(s[2*j2+1], aql[c], kh[1], kh[3]);
            }
        }

        float mx0 = -1e30f, mx1 = -1e30f;
        #pragma unroll
        for (int j = 0; j < 8; j++) {
            mx0 = fmaxf(mx0, fmaxf(s[j][0], s[j][1]));
            mx1 = fmaxf(mx1, fmaxf(s[j][2], s[j][3]));
        }
        mx0 = fmaxf(mx0, __shfl_xor_sync(0xffffffffu, mx0, 1));
        mx0 = fmaxf(mx0, __shfl_xor_sync(0xffffffffu, mx0, 2));
        mx1 = fmaxf(mx1, __shfl_xor_sync(0xffffffffu, mx1, 1));
        mx1 = fmaxf(mx1, __shfl_xor_sync(0xffffffffu, mx1, 2));
        float mn0 = fmaxf(m0, mx0), mn1 = fmaxf(m1, mx1);
        float corr0 = __expf(m0 - mn0), corr1 = __expf(m1 - mn1);
        m0 = mn0; m1 = mn1;

        float sum0 = 0.f, sum1 = 0.f;
        #pragma unroll
        for (int j = 0; j < 8; j++) {
            s[j][0] = __expf(s[j][0] - mn0); sum0 += s[j][0];
            s[j][1] = __expf(s[j][1] - mn0); sum0 += s[j][1];
            s[j][2] = __expf(s[j][2] - mn1); sum1 += s[j][2];
            s[j][3] = __expf(s[j][3] - mn1); sum1 += s[j][3];
        }
        sum0 += __shfl_xor_sync(0xffffffffu, sum0, 1);
        sum0 += __shfl_xor_sync(0xffffffffu, sum0, 2);
        sum1 += __shfl_xor_sync(0xffffffffu, sum1, 1);
        sum1 += __shfl_xor_sync(0xffffffffu, sum1, 2);
        l0 = l0 * corr0 + sum0;
        l1 = l1 * corr1 + sum1;

        #pragma unroll
        for (int j = 0; j < 8; j++) {
            o[j][0] *= corr0; o[j][1] *= corr0;
            o[j][2] *= corr1; o[j][3] *= corr1;
        }

        #pragma unroll
        for (int c = 0; c < 4; c++) {
            uint32_t ph[4], pl[4];
            split2(s[2*c][0],   s[2*c][1],   ph[0], pl[0]);
            split2(s[2*c][2],   s[2*c][3],   ph[1], pl[1]);
            split2(s[2*c+1][0], s[2*c+1][1], ph[2], pl[2]);
            split2(s[2*c+1][2], s[2*c+1][3], ph[3], pl[3]);
            #pragma unroll
            for (int j2 = 0; j2 < 4; j2++) {
                uint32_t vh[4], vl[4];
                uint32_t off = (uint32_t)((c * 16 + vb_row) * ASTR + j2 * 16 + vb_col) * 2;
                LDSM_X4_T(vh, sVhi + off);
                LDSM_X4_T(vl, sVlo + off);
                MMA_BF16(o[2*j2],   ph, vh[0], vh[1]);
                MMA_BF16(o[2*j2],   ph, vl[0], vl[1]);
                MMA_BF16(o[2*j2],   pl, vh[0], vh[1]);
                MMA_BF16(o[2*j2+1], ph, vh[2], vh[3]);
                MMA_BF16(o[2*j2+1], ph, vl[2], vl[3]);
                MMA_BF16(o[2*j2+1], pl, vh[2], vh[3]);
            }
        }
        __syncthreads();
    }

    float inv0 = 1.f / l0, inv1 = 1.f / l1;
    int qrow = q0blk + w * 16 + (lane >> 2);
    uint16_t* Ob0 = Oh + ((size_t)(n * SEQ) + qrow) * EMBED + h * 64 + (lane & 3) * 2;
    uint16_t* Ob1 = Ob0 + (size_t)8 * EMBED;
    #pragma unroll
    for (int j = 0; j < 8; j++) {
        *(uint32_t*)&Ob0[j * 8] = pack_f16(o[j][0] * inv0, o[j][1] * inv0);
        *(uint32_t*)&Ob1[j * 8] = pack_f16(o[j][2] * inv1, o[j][3] * inv1);
    }
}

// ==== tensor-core GEMM: A fp16 gmem, B pre-split fp16 hi/lo — all cp.async ====
#define GSTRIDE_A 40
#define GSTRIDE_B 136
#define ABUF (128 * GSTRIDE_A)    // 5120 elems
#define BBUF (32 * GSTRIDE_B)     // 4352 elems
#define GEMM_SMEM_BYTES ((2 * ABUF + 4 * BBUF) * 2)   // 55296

__global__ __launch_bounds__(256) void gemm_a16(
    const uint16_t* __restrict__ Ag,
    const uint16_t* __restrict__ BHg, const uint16_t* __restrict__ BLg,
    const float* __restrict__ bias,
    float* __restrict__ C32, uint16_t* __restrict__ C16,
    int M, int N, int K, int relu)
{
    extern __shared__ __align__(16) uint16_t dsm[];
    const int tid  = threadIdx.x;
    const int lane = tid & 31;
    const int wid  = tid >> 5;
    const int wm   = wid & 3;
    const int wn   = wid >> 2;
    const int bm   = blockIdx.y * 128;
    const int bn   = blockIdx.x * 128;

    const int ar  = tid >> 2, ac8 = (tid & 3) * 8;   // A: 64 rows per i-step
    const int br  = tid >> 4, bc8 = (tid & 15) * 8;  // B: 16 rows per i-step

    const int nk = K >> 5;
    const uint32_t s0 = (uint32_t)__cvta_generic_to_shared(dsm);

    // async-load k-block 0 into buffer 0
    {
        uint32_t dA  = s0 + (uint32_t)(ar * GSTRIDE_A + ac8) * 2;
        uint32_t dhi = s0 + (uint32_t)(2 * ABUF + br * GSTRIDE_B + bc8) * 2;
        uint32_t dlo = dhi + BBUF * 2;
        #pragma unroll
        for (int i = 0; i < 2; i++) {
            CP_ASYNC16(dA + i * 64 * GSTRIDE_A * 2, &Ag[(size_t)(bm + ar + i * 64) * K + ac8]);
            CP_ASYNC16(dhi + i * 16 * GSTRIDE_B * 2, &BHg[(size_t)(br + i * 16) * N + bn + bc8]);
            CP_ASYNC16(dlo + i * 16 * GSTRIDE_B * 2, &BLg[(size_t)(br + i * 16) * N + bn + bc8]);
        }
        CP_COMMIT;
        CP_WAIT0;
    }
    __syncthreads();

    float acc[2][8][4];
    #pragma unroll
    for (int m = 0; m < 2; m++)
        #pragma unroll
        for (int n = 0; n < 8; n++)
            #pragma unroll
            for (int c = 0; c < 4; c++) acc[m][n][c] = 0.f;

    const int a_row = wm * 32 + (lane & 15);
    const int a_koff = ((lane >> 4) & 1) * 8;
    const int b_krow = (lane & 15);
    const int b_coff = wn * 64 + ((lane >> 4) & 1) * 8;

    for (int kb = 0; kb < nk; kb++) {
        const int cur = kb & 1, nxt = cur ^ 1;
        const bool more = (kb + 1 < nk);

        if (more) {
            int k0 = (kb + 1) * 32;
            uint32_t dA  = s0 + (uint32_t)(nxt * ABUF + ar * GSTRIDE_A + ac8) * 2;
            uint32_t dhi = s0 + (uint32_t)(2 * ABUF + nxt * 2 * BBUF + br * GSTRIDE_B + bc8) * 2;
            uint32_t dlo = dhi + BBUF * 2;
            #pragma unroll
            for (int i = 0; i < 2; i++) {
                CP_ASYNC16(dA + i * 64 * GSTRIDE_A * 2, &Ag[(size_t)(bm + ar + i * 64) * K + k0 + ac8]);
                CP_ASYNC16(dhi + i * 16 * GSTRIDE_B * 2, &BHg[(size_t)(k0 + br + i * 16) * N + bn + bc8]);
                CP_ASYNC16(dlo + i * 16 * GSTRIDE_B * 2, &BLg[(size_t)(k0 + br + i * 16) * N + bn + bc8]);
            }
            CP_COMMIT;
        }

        const uint32_t bA   = s0 + (uint32_t)(cur * ABUF) * 2;
        const uint32_t bBhi = s0 + (uint32_t)(2 * ABUF + cur * 2 * BBUF) * 2;
        const uint32_t bBlo = bBhi + BBUF * 2;

        #pragma unroll
        for (int ks = 0; ks < 32; ks += 16) {
            uint32_t ah[2][4], bh[4][4], bl[4][4];
            #pragma unroll
            for (int m = 0; m < 2; m++) {
                uint32_t off = ((a_row + m * 16) * GSTRIDE_A + ks + a_koff) * 2;
                LDSM_X4(ah[m], bA + off);
            }
            #pragma unroll
            for (int j = 0; j < 4; j++) {
                uint32_t off = ((ks + b_krow) * GSTRIDE_B + b_coff + j * 16) * 2;
                LDSM_X4_T(bh[j], bBhi + off);
                LDSM_X4_T(bl[j], bBlo + off);
            }
            #pragma unroll
            for (int m = 0; m < 2; m++)
                #pragma unroll
                for (int j = 0; j < 4; j++)
                    #pragma unroll
                    for (int t = 0; t < 2; t++) {
                        int n = j * 2 + t;
                        MMA_F16(acc[m][n], ah[m], bh[j][2*t], bh[j][2*t+1]);
                        MMA_F16(acc[m][n], ah[m], bl[j][2*t], bl[j][2*t+1]);
                    }
        }

        if (more) {
            CP_WAIT0;
            __syncthreads();
        }
    }

    #pragma unroll
    for (int m = 0; m < 2; m++) {
        int row0 = bm + wm * 32 + m * 16 + (lane >> 2);
        #pragma unroll
        for (int n = 0; n < 8; n++) {
            int col = bn + wn * 64 + n * 8 + (lane & 3) * 2;
            float bx = bias[col], by = bias[col + 1];
            float2 v0 = make_float2(acc[m][n][0] + bx, acc[m][n][1] + by);
            float2 v1 = make_float2(acc[m][n][2] + bx, acc[m][n][3] + by);
            if (relu) {
                v0.x = fmaxf(v0.x, 0.f); v0.y = fmaxf(v0.y, 0.f);
                v1.x = fmaxf(v1.x, 0.f); v1.y = fmaxf(v1.y, 0.f);
            }
            if (C32) {
                *(float2*)&C32[(size_t)row0 * N + col]       = v0;
                *(float2*)&C32[(size_t)(row0 + 8) * N + col] = v1;
            }
            if (C16) {
                *(uint32_t*)&C16[(size_t)row0 * N + col]       = pack_f16(v0.x, v0.y);
                *(uint32_t*)&C16[(size_t)(row0 + 8) * N + col] = pack_f16(v1.x, v1.y);
            }
        }
    }
}

// -------- LayerNorm(A + R) * g + b : one pass; optional fp16 copy out ------
__global__ __launch_bounds__(256) void ln_kernel(
    const float* __restrict__ A, const float* __restrict__ R,
    const float* __restrict__ g, const float* __restrict__ b,
    float* __restrict__ Out, uint16_t* __restrict__ Out16)
{
    const int token = blockIdx.x, tid = threadIdx.x;
    const int lane = tid & 31, wid = tid >> 5;
    __shared__ float rs[8], rq[8];

    const float4 a = ((const float4*)A)[(size_t)token * 256 + tid];
    const float4 r = ((const float4*)R)[(size_t)token * 256 + tid];
    float4 v = make_float4(a.x + r.x, a.y + r.y, a.z + r.z, a.w + r.w);

    float sum = v.x + v.y + v.z + v.w;
    float sq  = v.x * v.x + v.y * v.y + v.z * v.z + v.w * v.w;
    #pragma unroll
    for (int off = 16; off > 0; off >>= 1) {
        sum += __shfl_xor_sync(0xffffffffu, sum, off);
        sq  += __shfl_xor_sync(0xffffffffu, sq,  off);
    }
    if (lane == 0) { rs[wid] = sum; rq[wid] = sq; }
    __syncthreads();
    if (tid == 0) {
        float S = 0.f, Qs = 0.f;
        #pragma unroll
        for (int i = 0; i < 8; i++) { S += rs[i]; Qs += rq[i]; }
        rs[0] = S; rq[0] = Qs;
    }
    __syncthreads();
    const float mean = rs[0] * (1.f / EMBED);
    const float var  = rq[0] * (1.f / EMBED) - mean * mean;
    const float rstd = rsqrtf(var + 1e-5f);

    const float4 gv = ((const float4*)g)[tid];
    const float4 bv = ((const float4*)b)[tid];
    float4 o;
    o.x = (v.x - mean) * rstd * gv.x + bv.x;
    o.y = (v.y - mean) * rstd * gv.y + bv.y;
    o.z = (v.z - mean) * rstd * gv.z + bv.z;
    o.w = (v.w - mean) * rstd * gv.w + bv.w;
    ((float4*)Out)[(size_t)token * 256 + tid] = o;
    if (Out16)
        ((uint2*)Out16)[(size_t)token * 256 + tid] =
            make_uint2(pack_f16(o.x, o.y), pack_f16(o.z, o.w));
}

// ---------------- launcher ----------------
extern "C" void kernel_launch(void* const* d_in, const int* in_sizes, int n_in,
                              void* d_out, int out_size)
{
    const float* x       = (const float*)d_in[0];
    const float* embed_W = (const float*)d_in[2];
    const float* embed_b = (const float*)d_in[3];
    const float* pe      = (const float*)d_in[4];
    const float* Wq      = (const float*)d_in[5];
    const float* Wk      = (const float*)d_in[6];
    const float* Wv      = (const float*)d_in[7];
    const float* Wo      = (const float*)d_in[8];
    const float* bo      = (const float*)d_in[9];
    const float* ln1_g   = (const float*)d_in[10];
    const float* ln1_b   = (const float*)d_in[11];
    const float* W1      = (const float*)d_in[12];
    const float* b1      = (const float*)d_in[13];
    const float* W2      = (const float*)d_in[14];
    const float* b2      = (const float*)d_in[15];
    const float* ln2_g   = (const float*)d_in[16];
    const float* ln2_b   = (const float*)d_in[17];

    static float *H = nullptr, *X1, *T, *Q, *K, *V;
    static uint16_t *Oh, *X1h, *Fh;
    static uint16_t *WoHi, *WoLo, *W1Hi, *W1Lo, *W2Hi, *W2Lo;
    if (!H) {
        cudaGetSymbolAddress((void**)&H,  g_H);
        cudaGetSymbolAddress((void**)&X1, g_X1);
        cudaGetSymbolAddress((void**)&T,  g_T);
        cudaGetSymbolAddress((void**)&Q,  g_Q);
        cudaGetSymbolAddress((void**)&K,  g_K);
        cudaGetSymbolAddress((void**)&V,  g_V);
        cudaGetSymbolAddress((void**)&Oh,  g_Oh);
        cudaGetSymbolAddress((void**)&X1h, g_X1h);
        cudaGetSymbolAddress((void**)&Fh,  g_Fh);
        cudaGetSymbolAddress((void**)&WoHi, g_WoHi);
        cudaGetSymbolAddress((void**)&WoLo, g_WoLo);
        cudaGetSymbolAddress((void**)&W1Hi, g_W1Hi);
        cudaGetSymbolAddress((void**)&W1Lo, g_W1Lo);
        cudaGetSymbolAddress((void**)&W2Hi, g_W2Hi);
        cudaGetSymbolAddress((void**)&W2Lo, g_W2Lo);
        cudaFuncSetAttribute(gemm_a16,
            cudaFuncAttributeMaxDynamicSharedMemorySize, GEMM_SMEM_BYTES);
        cudaFuncSetAttribute(qkv_tc_kernel,
            cudaFuncAttributeMaxDynamicSharedMemorySize, QKV_SMEM_BYTES);
    }

    {
        int n4o = 3 * EMBED * EMBED / 4;
        int n4f = 3 * EMBED * FFN_DIM / 4;
        wsplit_f16_kernel<<<(n4o + 255) / 256, 256>>>(Wo, WoHi, WoLo, n4o);
        wsplit_f16_kernel<<<(n4f + 255) / 256, 256>>>(W1, W1Hi, W1Lo, n4f);
        wsplit_f16_kernel<<<(n4f + 255) / 256, 256>>>(W2, W2Hi, W2Lo, n4f);
    }

    embed_kernel<<<TOKENS, 256>>>(x, embed_W, embed_b, pe, H);

    for (int l = 0; l < 3; l++) {
        qkv_tc_kernel<<<TOKENS / 8, 256, QKV_SMEM_BYTES>>>(H,
            Wq + (size_t)l * HDIM * HDIM,
            Wk + (size_t)l * HDIM * HDIM,
            Wv + (size_t)l * HDIM * HDIM,
            Q, K, V);

        attn_tc_kernel<<<dim3(SEQ / 128, BATCH * HEADS), 256>>>(Q, K, V, Oh);

        // T = Oh @ Wo + bo   (fp32 out)
        gemm_a16<<<dim3(EMBED / 128, TOKENS / 128), 256, GEMM_SMEM_BYTES>>>(
            Oh, WoHi + (size_t)l * EMBED * EMBED, WoLo + (size_t)l * EMBED * EMBED,
            bo + (size_t)l * EMBED, T, (uint16_t*)nullptr, TOKENS, EMBED, EMBED, 0);

        // X1 = LN(T + H)  (fp32 + fp16)
        ln_kernel<<<TOKENS, 256>>>(T, H,
            ln1_g + (size_t)l * EMBED, ln1_b + (size_t)l * EMBED, X1, X1h);

        // Fh = relu(X1h @ W1 + b1)   (fp16 out only)
        gemm_a16<<<dim3(FFN_DIM / 128, TOKENS / 128), 256, GEMM_SMEM_BYTES>>>(
            X1h, W1Hi + (size_t)l * EMBED * FFN_DIM, W1Lo + (size_t)l * EMBED * FFN_DIM,
            b1 + (size_t)l * FFN_DIM, (float*)nullptr, Fh, TOKENS, FFN_DIM, EMBED, 1);

        // T = Fh @ W2 + b2   (fp32 out)
        gemm_a16<<<dim3(EMBED / 128, TOKENS / 128), 256, GEMM_SMEM_BYTES>>>(
            Fh, W2Hi + (size_t)l * FFN_DIM * EMBED, W2Lo + (size_t)l * FFN_DIM * EMBED,
            b2 + (size_t)l * EMBED, T, (uint16_t*)nullptr, TOKENS, EMBED, FFN_DIM, 0);

        // H = LN(T + X1); last layer writes straight to d_out
        float* dst = (l == 2) ? (float*)d_out : H;
        ln_kernel<<<TOKENS, 256>>>(T, X1,
            ln2_g + (size_t)l * EMBED, ln2_b + (size_t)l * EMBED, dst,
            (uint16_t*)nullptr);
    }
    (void)in_sizes; (void)n_in; (void)out_size;
}

// round 10
// speedup vs baseline: 1.0192x; 1.0192x over previous
#include <cuda_runtime.h>
#include <cuda_bf16.h>
#include <cuda_fp16.h>
#include <cstdint>

#define BATCH   2
#define SEQ     2048
#define EMBED   1024
#define HEADS   16
#define HDIM    64
#define FFN_DIM 4096
#define TOKENS  (BATCH * SEQ)

// ---------------- scratch (no allocations allowed) ----------------
__device__ float g_H [TOKENS * EMBED];
__device__ float g_X1[TOKENS * EMBED];
__device__ float g_T [TOKENS * EMBED];
__device__ float g_O [TOKENS * EMBED];
__device__ float g_F [TOKENS * FFN_DIM];
// bf16 hi/lo QKV, layout [n][h][s][d]; Q pre-scaled by 1/32
__device__ uint16_t g_Qhi[TOKENS * EMBED];
__device__ uint16_t g_Qlo[TOKENS * EMBED];
__device__ uint16_t g_Khi[TOKENS * EMBED];
__device__ uint16_t g_Klo[TOKENS * EMBED];
__device__ uint16_t g_Vhi[TOKENS * EMBED];
__device__ uint16_t g_Vlo[TOKENS * EMBED];

// pre-split fp16 hi/lo weight copies (per layer, contiguous)
__device__ uint16_t g_WoHi[3 * EMBED * EMBED];
__device__ uint16_t g_WoLo[3 * EMBED * EMBED];
__device__ uint16_t g_W1Hi[3 * EMBED * FFN_DIM];
__device__ uint16_t g_W1Lo[3 * EMBED * FFN_DIM];
__device__ uint16_t g_W2Hi[3 * FFN_DIM * EMBED];
__device__ uint16_t g_W2Lo[3 * FFN_DIM * EMBED];

// ---------------- common helpers ----------------
__device__ __forceinline__ uint32_t pack_bf16(float x, float y) {
    __nv_bfloat162 h = __floats2bfloat162_rn(x, y);
    return *reinterpret_cast<uint32_t*>(&h);
}
__device__ __forceinline__ uint32_t pack_f16(float x, float y) {
    __half2 h = __floats2half2_rn(x, y);
    return *reinterpret_cast<uint32_t*>(&h);
}

__device__ __forceinline__ void split2(float x, float y, uint32_t& hi, uint32_t& lo) {
    float hx = __bfloat162float(__float2bfloat16_rn(x));
    float hy = __bfloat162float(__float2bfloat16_rn(y));
    hi = pack_bf16(hx, hy);
    lo = pack_bf16(x - hx, y - hy);
}

__device__ __forceinline__ void split_store4(uint16_t* Hi, uint16_t* Lo, int off, float4 v) {
    float h0 = __bfloat162float(__float2bfloat16_rn(v.x));
    float h1 = __bfloat162float(__float2bfloat16_rn(v.y));
    float h2 = __bfloat162float(__float2bfloat16_rn(v.z));
    float h3 = __bfloat162float(__float2bfloat16_rn(v.w));
    *(uint32_t*)&Hi[off]     = pack_bf16(h0, h1);
    *(uint32_t*)&Hi[off + 2] = pack_bf16(h2, h3);
    *(uint32_t*)&Lo[off]     = pack_bf16(v.x - h0, v.y - h1);
    *(uint32_t*)&Lo[off + 2] = pack_bf16(v.z - h2, v.w - h3);
}

__device__ __forceinline__ void f16_store4(uint16_t* Hi, int off, float4 v) {
    *(uint32_t*)&Hi[off]     = pack_f16(v.x, v.y);
    *(uint32_t*)&Hi[off + 2] = pack_f16(v.z, v.w);
}

#define MMA_BF16(d, a, b0, b1)                                              \
    asm volatile(                                                           \
        "mma.sync.aligned.m16n8k16.row.col.f32.bf16.bf16.f32 "              \
        "{%0,%1,%2,%3}, {%4,%5,%6,%7}, {%8,%9}, {%0,%1,%2,%3};"             \
        : "+f"(d[0]), "+f"(d[1]), "+f"(d[2]), "+f"(d[3])                    \
        : "r"(a[0]), "r"(a[1]), "r"(a[2]), "r"(a[3]), "r"(b0), "r"(b1))

#define MMA_F16(d, a, b0, b1)                                               \
    asm volatile(                                                           \
        "mma.sync.aligned.m16n8k16.row.col.f32.f16.f16.f32 "                \
        "{%0,%1,%2,%3}, {%4,%5,%6,%7}, {%8,%9}, {%0,%1,%2,%3};"             \
        : "+f"(d[0]), "+f"(d[1]), "+f"(d[2]), "+f"(d[3])                    \
        : "r"(a[0]), "r"(a[1]), "r"(a[2]), "r"(a[3]), "r"(b0), "r"(b1))

#define LDSM_X4(r, addr)                                                    \
    asm volatile("ldmatrix.sync.aligned.m8n8.x4.shared.b16 {%0,%1,%2,%3}, [%4];" \
        : "=r"(r[0]), "=r"(r[1]), "=r"(r[2]), "=r"(r[3]) : "r"(addr))

#define LDSM_X4_T(r, addr)                                                  \
    asm volatile("ldmatrix.sync.aligned.m8n8.x4.trans.shared.b16 {%0,%1,%2,%3}, [%4];" \
        : "=r"(r[0]), "=r"(r[1]), "=r"(r[2]), "=r"(r[3]) : "r"(addr))

#define CP_ASYNC16(dst, src)                                                \
    asm volatile("cp.async.cg.shared.global [%0], [%1], 16;" :: "r"(dst), "l"(src))
#define CP_COMMIT  asm volatile("cp.async.commit_group;")
#define CP_WAIT0   asm volatile("cp.async.wait_group 0;")
#define CP_WAIT1   asm volatile("cp.async.wait_group 1;")

// ---------------- weight pre-split: fp32 -> fp16 hi/lo ----------------
__global__ __launch_bounds__(256) void wsplit_f16_kernel(
    const float* __restrict__ src, uint16_t* __restrict__ hi,
    uint16_t* __restrict__ lo, int n4)
{
    int i = blockIdx.x * 256 + threadIdx.x;
    if (i >= n4) return;
    float4 v = ((const float4*)src)[i];
    float h0 = __half2float(__float2half_rn(v.x));
    float h1 = __half2float(__float2half_rn(v.y));
    float h2 = __half2float(__float2half_rn(v.z));
    float h3 = __half2float(__float2half_rn(v.w));
    ((uint2*)hi)[i] = make_uint2(pack_f16(h0, h1), pack_f16(h2, h3));
    ((uint2*)lo)[i] = make_uint2(pack_f16(v.x - h0, v.y - h1),
                                 pack_f16(v.z - h2, v.w - h3));
}

// ---------------- embed: H = x @ embed_W + embed_b + pe ----------------
__global__ __launch_bounds__(256) void embed_kernel(
    const float* __restrict__ X, const float* __restrict__ W,
    const float* __restrict__ b, const float* __restrict__ pe,
    float* __restrict__ H)
{
    int token = blockIdx.x;
    int s = token % SEQ;
    __shared__ float xs[64];
    int tid = threadIdx.x;
    if (tid < 64) xs[tid] = X[(size_t)token * 64 + tid];
    __syncthreads();
    #pragma unroll
    for (int j = 0; j < 4; j++) {
        int e = tid + j * 256;
        float acc = b[e] + pe[(size_t)s * EMBED + e];
        #pragma unroll 8
        for (int d = 0; d < 64; d++)
            acc += xs[d] * W[(size_t)d * EMBED + e];
        H[(size_t)token * EMBED + e] = acc;
    }
}

// ======== tensor-core QKV -> bf16 hi/lo outputs (Q pre-scaled 1/32) ========
#define QSTR 72
#define QKV_W_OFF    (2 * 128 * QSTR)
#define QKV_SMEM_BYTES ((2 * 128 * QSTR + 6 * 64 * QSTR) * 2)

__global__ __launch_bounds__(256) void qkv_tc_kernel(
    const float* __restrict__ H,
    const float* __restrict__ Wq, const float* __restrict__ Wk,
    const float* __restrict__ Wv,
    uint16_t* __restrict__ Qhi, uint16_t* __restrict__ Qlo,
    uint16_t* __restrict__ Khi, uint16_t* __restrict__ Klo,
    uint16_t* __restrict__ Vhi, uint16_t* __restrict__ Vlo)
{
    extern __shared__ __align__(16) uint16_t qsm[];
    uint16_t* Ahi = qsm;
    uint16_t* Alo = qsm + 128 * QSTR;
    uint16_t* Wb  = qsm + QKV_W_OFF;

    const int tid = threadIdx.x, lane = tid & 31, w = tid >> 5;
    const int t0 = blockIdx.x * 8;

    #pragma unroll
    for (int i = 0; i < 8; i++) {
        int idx = i * 256 + tid;
        int row = idx >> 4, c4 = (idx & 15) * 4;
        float4 v = *(const float4*)&H[(size_t)(t0 + (row >> 4)) * EMBED
                                      + (row & 15) * 64 + c4];
        split_store4(Ahi, Alo, row * QSTR + c4, v);
    }
    #pragma unroll
    for (int i = 0; i < 12; i++) {
        int idx = i * 256 + tid;
        int which = idx >> 10;
        int rem = idx & 1023;
        int row = rem >> 4, c4 = (rem & 15) * 4;
        const float* Wp = (which == 0) ? Wq : (which == 1) ? Wk : Wv;
        float4 v = *(const float4*)&Wp[row * 64 + c4];
        uint16_t* hi = Wb + which * 2 * 64 * QSTR;
        uint16_t* lo = hi + 64 * QSTR;
        split_store4(hi, lo, row * QSTR + c4, v);
    }
    __syncthreads();

    const uint32_t sA  = (uint32_t)__cvta_generic_to_shared(Ahi);
    const uint32_t sAl = (uint32_t)__cvta_generic_to_shared(Alo);
    const uint32_t sW  = (uint32_t)__cvta_generic_to_shared(Wb);

    uint32_t ah[4][4], al[4][4];
    {
        int arow = w * 16 + (lane & 15);
        int aoff = ((lane >> 4) & 1) * 8;
        #pragma unroll
        for (int c = 0; c < 4; c++) {
            uint32_t off = (uint32_t)(arow * QSTR + c * 16 + aoff) * 2;
            LDSM_X4(ah[c], sA + off);
            LDSM_X4(al[c], sAl + off);
        }
    }

    const int b_krow = lane & 15;
    const int b_coff = ((lane >> 4) & 1) * 8;

    const int gt = t0 + w;
    const int n = gt >> 11, s = gt & (SEQ - 1);
    const int ha = lane >> 2, hb = ha + 8;
    const int cbase = (lane & 3) * 2;

    uint16_t* outs_hi[3] = {Qhi, Khi, Vhi};
    uint16_t* outs_lo[3] = {Qlo, Klo, Vlo};
    #pragma unroll
    for (int mat = 0; mat < 3; mat++) {
        const uint32_t bh_base = sW + (uint32_t)(mat * 2 * 64 * QSTR) * 2;
        const uint32_t bl_base = bh_base + (uint32_t)(64 * QSTR) * 2;

        float acc[8][4];
        #pragma unroll
        for (int j = 0; j < 8; j++)
            #pragma unroll
            for (int c = 0; c < 4; c++) acc[j][c] = 0.f;

        #pragma unroll
        for (int c = 0; c < 4; c++) {
            #pragma unroll
            for (int j2 = 0; j2 < 4; j2++) {
                uint32_t bh[4], bl[4];
                uint32_t off = (uint32_t)((c * 16 + b_krow) * QSTR + j2 * 16 + b_coff) * 2;
                LDSM_X4_T(bh, bh_base + off);
                LDSM_X4_T(bl, bl_base + off);
                #pragma unroll
                for (int t = 0; t < 2; t++) {
                    int j = j2 * 2 + t;
                    MMA_BF16(acc[j], ah[c], bh[2*t], bh[2*t+1]);
                    MMA_BF16(acc[j], ah[c], bl[2*t], bl[2*t+1]);
                    MMA_BF16(acc[j], al[c], bh[2*t], bh[2*t+1]);
                }
            }
        }

        const float scale = (mat == 0) ? 0.03125f : 1.0f;
        uint16_t* ph = outs_hi[mat] + (((size_t)(n * HEADS + ha) * SEQ + s)) * HDIM + cbase;
        uint16_t* pl = outs_lo[mat] + (((size_t)(n * HEADS + ha) * SEQ + s)) * HDIM + cbase;
        uint16_t* qh = outs_hi[mat] + (((size_t)(n * HEADS + hb) * SEQ + s)) * HDIM + cbase;
        uint16_t* ql = outs_lo[mat] + (((size_t)(n * HEADS + hb) * SEQ + s)) * HDIM + cbase;
        #pragma unroll
        for (int j = 0; j < 8; j++) {
            uint32_t hi0, lo0, hi1, lo1;
            split2(acc[j][0] * scale, acc[j][1] * scale, hi0, lo0);
            split2(acc[j][2] * scale, acc[j][3] * scale, hi1, lo1);
            *(uint32_t*)&ph[j * 8] = hi0;
            *(uint32_t*)&pl[j * 8] = lo0;
            *(uint32_t*)&qh[j * 8] = hi1;
            *(uint32_t*)&ql[j * 8] = lo1;
        }
    }
}

// ===== tensor-core flash attention: bf16 hi/lo K/V streamed via cp.async ====
#define ASTR 72
#define KVSTG (4 * 64 * ASTR)                 // elems per K/V stage
#define ATT_SMEM_BYTES (2 * KVSTG * 2)        // 73728 B

__global__ __launch_bounds__(256, 1) void attn_tc_kernel(
    const uint16_t* __restrict__ Qhi_g, const uint16_t* __restrict__ Qlo_g,
    const uint16_t* __restrict__ Khi_g, const uint16_t* __restrict__ Klo_g,
    const uint16_t* __restrict__ Vhi_g, const uint16_t* __restrict__ Vlo_g,
    float* __restrict__ O)
{
    extern __shared__ __align__(16) uint16_t asmm[];
    const int tid = threadIdx.x, lane = tid & 31, w = tid >> 5;
    const int nh = blockIdx.y;
    const int n = nh >> 4, h = nh & 15;
    const int q0blk = blockIdx.x * 128;

    const uint32_t s0 = (uint32_t)__cvta_generic_to_shared(asmm);
    const size_t nhbase = (size_t)nh * SEQ * HDIM;

    // stage Q tile (hi+lo) into stage-1 area via cp.async
    {
        #pragma unroll
        for (int i = 0; i < 8; i++) {
            int idx = i * 256 + tid;
            int t = idx >> 10, r = (idx >> 3) & 127, c = (idx & 7) * 8;
            const uint16_t* src = (t ? Qlo_g : Qhi_g)
                + nhbase + (size_t)(q0blk + r) * HDIM + c;
            uint32_t dst = s0 + (uint32_t)(KVSTG + t * 128 * ASTR + r * ASTR + c) * 2;
            CP_ASYNC16(dst, src);
        }
        CP_COMMIT;
    }
    // issue K/V block 0 into stage 0
    const uint16_t* kvbase[4] = {Khi_g + nhbase, Klo_g + nhbase,
                                 Vhi_g + nhbase, Vlo_g + nhbase};
    {
        #pragma unroll
        for (int i = 0; i < 8; i++) {
            int idx = i * 256 + tid;
            int t = idx >> 9, r = (idx >> 3) & 63, c = (idx & 7) * 8;
            CP_ASYNC16(s0 + (uint32_t)(t * 64 * ASTR + r * ASTR + c) * 2,
                       kvbase[t] + (size_t)r * HDIM + c);
        }
        CP_COMMIT;
    }

    CP_WAIT1;                 // Q done (K/V block 0 may be in flight)
    __syncthreads();

    // Q fragments from stage-1 area
    uint32_t aqh[4][4], aql[4][4];
    {
        int arow = w * 16 + (lane & 15);
        int aoff = ((lane >> 4) & 1) * 8;
        #pragma unroll
        for (int c = 0; c < 4; c++) {
            uint32_t off = (uint32_t)(KVSTG + arow * ASTR + c * 16 + aoff) * 2;
            LDSM_X4(aqh[c], s0 + off);
            LDSM_X4(aql[c], s0 + off + (uint32_t)(128 * ASTR) * 2);
        }
    }
    __syncthreads();          // Q reads done; stage 1 free for K/V

    float o[8][4];
    #pragma unroll
    for (int j = 0; j < 8; j++)
        #pragma unroll
        for (int c = 0; c < 4; c++) o[j][c] = 0.f;
    float m0 = -1e30f, m1 = -1e30f, l0 = 0.f, l1 = 0.f;

    const int kb_row = lane & 15;
    const int kb_col = ((lane >> 4) & 1) * 8;

    for (int kb = 0; kb < SEQ / 64; kb++) {
        const int cur = kb & 1;
        const bool more = (kb + 1 < SEQ / 64);

        if (more) {
            int nxt = cur ^ 1;
            size_t blk = (size_t)(kb + 1) * 64 * HDIM;
            #pragma unroll
            for (int i = 0; i < 8; i++) {
                int idx = i * 256 + tid;
                int t = idx >> 9, r = (idx >> 3) & 63, c = (idx & 7) * 8;
                CP_ASYNC16(s0 + (uint32_t)(nxt * KVSTG + t * 64 * ASTR + r * ASTR + c) * 2,
                           kvbase[t] + blk + (size_t)r * HDIM + c);
            }
            CP_COMMIT;
            CP_WAIT1;
        } else {
            CP_WAIT0;
        }
        __syncthreads();

        const uint32_t sKhi = s0 + (uint32_t)(cur * KVSTG) * 2;
        const uint32_t sKlo = sKhi + (uint32_t)(64 * ASTR) * 2;
        const uint32_t sVhi = sKhi + (uint32_t)(2 * 64 * ASTR) * 2;
        const uint32_t sVlo = sKhi + (uint32_t)(3 * 64 * ASTR) * 2;

        // ---- S = Q K^T ----
        float s[8][4];
        #pragma unroll
        for (int j = 0; j < 8; j++)
            #pragma unroll
            for (int c = 0; c < 4; c++) s[j][c] = 0.f;

        #pragma unroll
        for (int c = 0; c < 4; c++) {
            #pragma unroll
            for (int j2 = 0; j2 < 4; j2++) {
                uint32_t kh[4], kl[4];
                uint32_t off = (uint32_t)((j2 * 16 + kb_row) * ASTR + c * 16 + kb_col) * 2;
                LDSM_X4(kh, sKhi + off);
                LDSM_X4(kl, sKlo + off);
                MMA_BF16(s[2*j2],   aqh[c], kh[0], kh[2]);
                MMA_BF16(s[2*j2],   aqh[c], kl[0], kl[2]);
                MMA_BF16(s[2*j2],   aql[c], kh[0], kh[2]);
                MMA_BF16(s[2*j2+1], aqh[c], kh[1], kh[3]);
                MMA_BF16(s[2*j2+1], aqh[c], kl[1], kl[3]);
                MMA_BF16(s[2*j2+1], aql[c], kh[1], kh[3]);
            }
        }

        // ---- online softmax ----
        float mx0 = -1e30f, mx1 = -1e30f;
        #pragma unroll
        for (int j = 0; j < 8; j++) {
            mx0 = fmaxf(mx0, fmaxf(s[j][0], s[j][1]));
            mx1 = fmaxf(mx1, fmaxf(s[j][2], s[j][3]));
        }
        mx0 = fmaxf(mx0, __shfl_xor_sync(0xffffffffu, mx0, 1));
        mx0 = fmaxf(mx0, __shfl_xor_sync(0xffffffffu, mx0, 2));
        mx1 = fmaxf(mx1, __shfl_xor_sync(0xffffffffu, mx1, 1));
        mx1 = fmaxf(mx1, __shfl_xor_sync(0xffffffffu, mx1, 2));
        float mn0 = fmaxf(m0, mx0), mn1 = fmaxf(m1, mx1);
        float corr0 = __expf(m0 - mn0), corr1 = __expf(m1 - mn1);
        m0 = mn0; m1 = mn1;

        float sum0 = 0.f, sum1 = 0.f;
        #pragma unroll
        for (int j = 0; j < 8; j++) {
            s[j][0] = __expf(s[j][0] - mn0); sum0 += s[j][0];
            s[j][1] = __expf(s[j][1] - mn0); sum0 += s[j][1];
            s[j][2] = __expf(s[j][2] - mn1); sum1 += s[j][2];
            s[j][3] = __expf(s[j][3] - mn1); sum1 += s[j][3];
        }
        sum0 += __shfl_xor_sync(0xffffffffu, sum0, 1);
        sum0 += __shfl_xor_sync(0xffffffffu, sum0, 2);
        sum1 += __shfl_xor_sync(0xffffffffu, sum1, 1);
        sum1 += __shfl_xor_sync(0xffffffffu, sum1, 2);
        l0 = l0 * corr0 + sum0;
        l1 = l1 * corr1 + sum1;

        #pragma unroll
        for (int j = 0; j < 8; j++) {
            o[j][0] *= corr0; o[j][1] *= corr0;
            o[j][2] *= corr1; o[j][3] *= corr1;
        }

        // ---- O += P V ----
        #pragma unroll
        for (int c = 0; c < 4; c++) {
            uint32_t ph[4], pl[4];
            split2(s[2*c][0],   s[2*c][1],   ph[0], pl[0]);
            split2(s[2*c][2],   s[2*c][3],   ph[1], pl[1]);
            split2(s[2*c+1][0], s[2*c+1][1], ph[2], pl[2]);
            split2(s[2*c+1][2], s[2*c+1][3], ph[3], pl[3]);
            #pragma unroll
            for (int j2 = 0; j2 < 4; j2++) {
                uint32_t vh[4], vl[4];
                uint32_t off = (uint32_t)((c * 16 + kb_row) * ASTR + j2 * 16 + kb_col) * 2;
                LDSM_X4_T(vh, sVhi + off);
                LDSM_X4_T(vl, sVlo + off);
                MMA_BF16(o[2*j2],   ph, vh[0], vh[1]);
                MMA_BF16(o[2*j2],   ph, vl[0], vl[1]);
                MMA_BF16(o[2*j2],   pl, vh[0], vh[1]);
                MMA_BF16(o[2*j2+1], ph, vh[2], vh[3]);
                MMA_BF16(o[2*j2+1], ph, vl[2], vl[3]);
                MMA_BF16(o[2*j2+1], pl, vh[2], vh[3]);
            }
        }
        __syncthreads();      // all reads of buffer cur done before overwrite
    }

    float inv0 = 1.f / l0, inv1 = 1.f / l1;
    int qrow = q0blk + w * 16 + (lane >> 2);
    float* Ob0 = O + ((size_t)(n * SEQ) + qrow) * EMBED + h * 64 + (lane & 3) * 2;
    float* Ob1 = Ob0 + (size_t)8 * EMBED;
    #pragma unroll
    for (int j = 0; j < 8; j++) {
        *(float2*)&Ob0[j * 8] = make_float2(o[j][0] * inv0, o[j][1] * inv0);
        *(float2*)&Ob1[j * 8] = make_float2(o[j][2] * inv1, o[j][3] * inv1);
    }
}

// ==== tensor-core GEMM (R8-proven): A fp32 LDG+cvt, B cp.async fp16 hi/lo ====
#define GSTRIDE_A 40
#define GSTRIDE_B 136
#define ABUF (128 * GSTRIDE_A)
#define BBUF (32 * GSTRIDE_B)
#define GEMM_SMEM_BYTES ((2 * ABUF + 4 * BBUF) * 2)   // 55296

__global__ __launch_bounds__(256) void gemm_tc_f16(
    const float* __restrict__ A,
    const uint16_t* __restrict__ BHg, const uint16_t* __restrict__ BLg,
    const float* __restrict__ bias, float* __restrict__ C,
    int M, int N, int K, int relu)
{
    extern __shared__ __align__(16) uint16_t dsm[];
    const int tid  = threadIdx.x;
    const int lane = tid & 31;
    const int wid  = tid >> 5;
    const int wm   = wid & 3;
    const int wn   = wid >> 2;
    const int bm   = blockIdx.y * 128;
    const int bn   = blockIdx.x * 128;

    const int ar  = tid >> 3, ac4 = (tid & 7) * 4;
    const int br  = tid >> 4, bc8 = (tid & 15) * 8;

    float4 pa[4];
    const int nk = K >> 5;
    const uint32_t s0 = (uint32_t)__cvta_generic_to_shared(dsm);

    {
        uint32_t dhi = s0 + (uint32_t)(2 * ABUF + br * GSTRIDE_B + bc8) * 2;
        uint32_t dlo = dhi + BBUF * 2;
        #pragma unroll
        for (int i = 0; i < 2; i++) {
            CP_ASYNC16(dhi + i * 16 * GSTRIDE_B * 2, &BHg[(size_t)(br + i * 16) * N + bn + bc8]);
            CP_ASYNC16(dlo + i * 16 * GSTRIDE_B * 2, &BLg[(size_t)(br + i * 16) * N + bn + bc8]);
        }
        CP_COMMIT;
        #pragma unroll
        for (int i = 0; i < 4; i++)
            pa[i] = *(const float4*)&A[(size_t)(bm + ar + i * 32) * K + ac4];
        #pragma unroll
        for (int i = 0; i < 4; i++)
            f16_store4(dsm, (ar + i * 32) * GSTRIDE_A + ac4, pa[i]);
        CP_WAIT0;
    }
    __syncthreads();

    float acc[2][8][4];
    #pragma unroll
    for (int m = 0; m < 2; m++)
        #pragma unroll
        for (int n = 0; n < 8; n++)
            #pragma unroll
            for (int c = 0; c < 4; c++) acc[m][n][c] = 0.f;

    const int a_row = wm * 32 + (lane & 15);
    const int a_koff = ((lane >> 4) & 1) * 8;
    const int b_krow = (lane & 15);
    const int b_coff = wn * 64 + ((lane >> 4) & 1) * 8;

    for (int kb = 0; kb < nk; kb++) {
        const int cur = kb & 1, nxt = cur ^ 1;
        const bool more = (kb + 1 < nk);

        if (more) {
            int k0 = (kb + 1) * 32;
            uint32_t dhi = s0 + (uint32_t)(2 * ABUF + nxt * 2 * BBUF + br * GSTRIDE_B + bc8) * 2;
            uint32_t dlo = dhi + BBUF * 2;
            #pragma unroll
            for (int i = 0; i < 2; i++) {
                CP_ASYNC16(dhi + i * 16 * GSTRIDE_B * 2, &BHg[(size_t)(k0 + br + i * 16) * N + bn + bc8]);
                CP_ASYNC16(dlo + i * 16 * GSTRIDE_B * 2, &BLg[(size_t)(k0 + br + i * 16) * N + bn + bc8]);
            }
            CP_COMMIT;
            #pragma unroll
            for (int i = 0; i < 4; i++)
                pa[i] = *(const float4*)&A[(size_t)(bm + ar + i * 32) * K + k0 + ac4];
        }

        const uint32_t bA   = s0 + (uint32_t)(cur * ABUF) * 2;
        const uint32_t bBhi = s0 + (uint32_t)(2 * ABUF + cur * 2 * BBUF) * 2;
        const uint32_t bBlo = bBhi + BBUF * 2;

        #pragma unroll
        for (int ks = 0; ks < 32; ks += 16) {
            uint32_t ah[2][4], bh[4][4], bl[4][4];
            #pragma unroll
            for (int m = 0; m < 2; m++) {
                uint32_t off = ((a_row + m * 16) * GSTRIDE_A + ks + a_koff) * 2;
                LDSM_X4(ah[m], bA + off);
            }
            #pragma unroll
            for (int j = 0; j < 4; j++) {
                uint32_t off = ((ks + b_krow) * GSTRIDE_B + b_coff + j * 16) * 2;
                LDSM_X4_T(bh[j], bBhi + off);
                LDSM_X4_T(bl[j], bBlo + off);
            }
            #pragma unroll
            for (int m = 0; m < 2; m++)
                #pragma unroll
                for (int j = 0; j < 4; j++)
                    #pragma unroll
                    for (int t = 0; t < 2; t++) {
                        int n = j * 2 + t;
                        MMA_F16(acc[m][n], ah[m], bh[j][2*t], bh[j][2*t+1]);
                        MMA_F16(acc[m][n], ah[m], bl[j][2*t], bl[j][2*t+1]);
                    }
        }

        if (more) {
            uint16_t* Ah = dsm + nxt * ABUF;
            #pragma unroll
            for (int i = 0; i < 4; i++)
                f16_store4(Ah, (ar + i * 32) * GSTRIDE_A + ac4, pa[i]);
            CP_WAIT0;
            __syncthreads();
        }
    }

    #pragma unroll
    for (int m = 0; m < 2; m++) {
        int row0 = bm + wm * 32 + m * 16 + (lane >> 2);
        #pragma unroll
        for (int n = 0; n < 8; n++) {
            int col = bn + wn * 64 + n * 8 + (lane & 3) * 2;
            float bx = bias[col], by = bias[col + 1];
            float2 v0 = make_float2(acc[m][n][0] + bx, acc[m][n][1] + by);
            float2 v1 = make_float2(acc[m][n][2] + bx, acc[m][n][3] + by);
            if (relu) {
                v0.x = fmaxf(v0.x, 0.f); v0.y = fmaxf(v0.y, 0.f);
                v1.x = fmaxf(v1.x, 0.f); v1.y = fmaxf(v1.y, 0.f);
            }
            *(float2*)&C[(size_t)row0 * N + col]       = v0;
            *(float2*)&C[(size_t)(row0 + 8) * N + col] = v1;
        }
    }
}

// ---------------- LayerNorm(A + R) * g + b : one pass, reg-resident -------
__global__ __launch_bounds__(256) void ln_kernel(
    const float* __restrict__ A, const float* __restrict__ R,
    const float* __restrict__ g, const float* __restrict__ b,
    float* __restrict__ Out)
{
    const int token = blockIdx.x, tid = threadIdx.x;
    const int lane = tid & 31, wid = tid >> 5;
    __shared__ float rs[8], rq[8];

    const float4 a = ((const float4*)A)[(size_t)token * 256 + tid];
    const float4 r = ((const float4*)R)[(size_t)token * 256 + tid];
    float4 v = make_float4(a.x + r.x, a.y + r.y, a.z + r.z, a.w + r.w);

    float sum = v.x + v.y + v.z + v.w;
    float sq  = v.x * v.x + v.y * v.y + v.z * v.z + v.w * v.w;
    #pragma unroll
    for (int off = 16; off > 0; off >>= 1) {
        sum += __shfl_xor_sync(0xffffffffu, sum, off);
        sq  += __shfl_xor_sync(0xffffffffu, sq,  off);
    }
    if (lane == 0) { rs[wid] = sum; rq[wid] = sq; }
    __syncthreads();
    if (tid == 0) {
        float S = 0.f, Qs = 0.f;
        #pragma unroll
        for (int i = 0; i < 8; i++) { S += rs[i]; Qs += rq[i]; }
        rs[0] = S; rq[0] = Qs;
    }
    __syncthreads();
    const float mean = rs[0] * (1.f / EMBED);
    const float var  = rq[0] * (1.f / EMBED) - mean * mean;
    const float rstd = rsqrtf(var + 1e-5f);

    const float4 gv = ((const float4*)g)[tid];
    const float4 bv = ((const float4*)b)[tid];
    float4 o;
    o.x = (v.x - mean) * rstd * gv.x + bv.x;
    o.y = (v.y - mean) * rstd * gv.y + bv.y;
    o.z = (v.z - mean) * rstd * gv.z + bv.z;
    o.w = (v.w - mean) * rstd * gv.w + bv.w;
    ((float4*)Out)[(size_t)token * 256 + tid] = o;
}

// ---------------- launcher ----------------
extern "C" void kernel_launch(void* const* d_in, const int* in_sizes, int n_in,
                              void* d_out, int out_size)
{
    const float* x       = (const float*)d_in[0];
    const float* embed_W = (const float*)d_in[2];
    const float* embed_b = (const float*)d_in[3];
    const float* pe      = (const float*)d_in[4];
    const float* Wq      = (const float*)d_in[5];
    const float* Wk      = (const float*)d_in[6];
    const float* Wv      = (const float*)d_in[7];
    const float* Wo      = (const float*)d_in[8];
    const float* bo      = (const float*)d_in[9];
    const float* ln1_g   = (const float*)d_in[10];
    const float* ln1_b   = (const float*)d_in[11];
    const float* W1      = (const float*)d_in[12];
    const float* b1      = (const float*)d_in[13];
    const float* W2      = (const float*)d_in[14];
    const float* b2      = (const float*)d_in[15];
    const float* ln2_g   = (const float*)d_in[16];
    const float* ln2_b   = (const float*)d_in[17];

    static float *H = nullptr, *X1, *T, *O, *F;
    static uint16_t *Qhi, *Qlo, *Khi, *Klo, *Vhi, *Vlo;
    static uint16_t *WoHi, *WoLo, *W1Hi, *W1Lo, *W2Hi, *W2Lo;
    if (!H) {
        cudaGetSymbolAddress((void**)&H,  g_H);
        cudaGetSymbolAddress((void**)&X1, g_X1);
        cudaGetSymbolAddress((void**)&T,  g_T);
        cudaGetSymbolAddress((void**)&O,  g_O);
        cudaGetSymbolAddress((void**)&F,  g_F);
        cudaGetSymbolAddress((void**)&Qhi, g_Qhi);
        cudaGetSymbolAddress((void**)&Qlo, g_Qlo);
        cudaGetSymbolAddress((void**)&Khi, g_Khi);
        cudaGetSymbolAddress((void**)&Klo, g_Klo);
        cudaGetSymbolAddress((void**)&Vhi, g_Vhi);
        cudaGetSymbolAddress((void**)&Vlo, g_Vlo);
        cudaGetSymbolAddress((void**)&WoHi, g_WoHi);
        cudaGetSymbolAddress((void**)&WoLo, g_WoLo);
        cudaGetSymbolAddress((void**)&W1Hi, g_W1Hi);
        cudaGetSymbolAddress((void**)&W1Lo, g_W1Lo);
        cudaGetSymbolAddress((void**)&W2Hi, g_W2Hi);
        cudaGetSymbolAddress((void**)&W2Lo, g_W2Lo);
        cudaFuncSetAttribute(gemm_tc_f16,
            cudaFuncAttributeMaxDynamicSharedMemorySize, GEMM_SMEM_BYTES);
        cudaFuncSetAttribute(qkv_tc_kernel,
            cudaFuncAttributeMaxDynamicSharedMemorySize, QKV_SMEM_BYTES);
        cudaFuncSetAttribute(attn_tc_kernel,
            cudaFuncAttributeMaxDynamicSharedMemorySize, ATT_SMEM_BYTES);
    }

    {
        int n4o = 3 * EMBED * EMBED / 4;
        int n4f = 3 * EMBED * FFN_DIM / 4;
        wsplit_f16_kernel<<<(n4o + 255) / 256, 256>>>(Wo, WoHi, WoLo, n4o);
        wsplit_f16_kernel<<<(n4f + 255) / 256, 256>>>(W1, W1Hi, W1Lo, n4f);
        wsplit_f16_kernel<<<(n4f + 255) / 256, 256>>>(W2, W2Hi, W2Lo, n4f);
    }

    embed_kernel<<<TOKENS, 256>>>(x, embed_W, embed_b, pe, H);

    for (int l = 0; l < 3; l++) {
        qkv_tc_kernel<<<TOKENS / 8, 256, QKV_SMEM_BYTES>>>(H,
            Wq + (size_t)l * HDIM * HDIM,
            Wk + (size_t)l * HDIM * HDIM,
            Wv + (size_t)l * HDIM * HDIM,
            Qhi, Qlo, Khi, Klo, Vhi, Vlo);

        attn_tc_kernel<<<dim3(SEQ / 128, BATCH * HEADS), 256, ATT_SMEM_BYTES>>>(
            Qhi, Qlo, Khi, Klo, Vhi, Vlo, O);

        gemm_tc_f16<<<dim3(EMBED / 128, TOKENS / 128), 256, GEMM_SMEM_BYTES>>>(
            O, WoHi + (size_t)l * EMBED * EMBED, WoLo + (size_t)l * EMBED * EMBED,
            bo + (size_t)l * EMBED, T, TOKENS, EMBED, EMBED, 0);

        ln_kernel<<<TOKENS, 256>>>(T, H,
            ln1_g + (size_t)l * EMBED, ln1_b + (size_t)l * EMBED, X1);

        gemm_tc_f16<<<dim3(FFN_DIM / 128, TOKENS / 128), 256, GEMM_SMEM_BYTES>>>(
            X1, W1Hi + (size_t)l * EMBED * FFN_DIM, W1Lo + (size_t)l * EMBED * FFN_DIM,
            b1 + (size_t)l * FFN_DIM, F, TOKENS, FFN_DIM, EMBED, 1);

        gemm_tc_f16<<<dim3(EMBED / 128, TOKENS / 128), 256, GEMM_SMEM_BYTES>>>(
            F, W2Hi + (size_t)l * FFN_DIM * EMBED, W2Lo + (size_t)l * FFN_DIM * EMBED,
            b2 + (size_t)l * EMBED, T, TOKENS, EMBED, FFN_DIM, 0);

        float* dst = (l == 2) ? (float*)d_out : H;
        ln_kernel<<<TOKENS, 256>>>(T, X1,
            ln2_g + (size_t)l * EMBED, ln2_b + (size_t)l * EMBED, dst);
    }
    (void)in_sizes; (void)n_in; (void)out_size;
}

// round 11
// speedup vs baseline: 1.0305x; 1.0111x over previous
#include <cuda_runtime.h>
#include <cuda_bf16.h>
#include <cuda_fp16.h>
#include <cstdint>

#define BATCH   2
#define SEQ     2048
#define EMBED   1024
#define HEADS   16
#define HDIM    64
#define FFN_DIM 4096
#define TOKENS  (BATCH * SEQ)

// ---------------- scratch (no allocations allowed) ----------------
__device__ float g_H [TOKENS * EMBED];
__device__ float g_X1[TOKENS * EMBED];
__device__ float g_T [TOKENS * EMBED];
__device__ float g_O [TOKENS * EMBED];
__device__ float g_F [TOKENS * FFN_DIM];
// bf16 hi/lo QKV, layout [n][h][s][d]; Q pre-scaled by 1/32
__device__ uint16_t g_Qhi[TOKENS * EMBED];
__device__ uint16_t g_Qlo[TOKENS * EMBED];
__device__ uint16_t g_Khi[TOKENS * EMBED];
__device__ uint16_t g_Klo[TOKENS * EMBED];
__device__ uint16_t g_Vhi[TOKENS * EMBED];
__device__ uint16_t g_Vlo[TOKENS * EMBED];

// pre-split fp16 hi/lo weight copies (per layer, contiguous)
__device__ uint16_t g_WoHi[3 * EMBED * EMBED];
__device__ uint16_t g_WoLo[3 * EMBED * EMBED];
__device__ uint16_t g_W1Hi[3 * EMBED * FFN_DIM];
__device__ uint16_t g_W1Lo[3 * EMBED * FFN_DIM];
__device__ uint16_t g_W2Hi[3 * FFN_DIM * EMBED];
__device__ uint16_t g_W2Lo[3 * FFN_DIM * EMBED];
// pre-split bf16 hi/lo embed weight
__device__ uint16_t g_EWHi[INT32_C(64) * EMBED];
__device__ uint16_t g_EWLo[INT32_C(64) * EMBED];

// ---------------- common helpers ----------------
__device__ __forceinline__ uint32_t pack_bf16(float x, float y) {
    __nv_bfloat162 h = __floats2bfloat162_rn(x, y);
    return *reinterpret_cast<uint32_t*>(&h);
}
__device__ __forceinline__ uint32_t pack_f16(float x, float y) {
    __half2 h = __floats2half2_rn(x, y);
    return *reinterpret_cast<uint32_t*>(&h);
}

__device__ __forceinline__ void split2(float x, float y, uint32_t& hi, uint32_t& lo) {
    float hx = __bfloat162float(__float2bfloat16_rn(x));
    float hy = __bfloat162float(__float2bfloat16_rn(y));
    hi = pack_bf16(hx, hy);
    lo = pack_bf16(x - hx, y - hy);
}

__device__ __forceinline__ void split_store4(uint16_t* Hi, uint16_t* Lo, int off, float4 v) {
    float h0 = __bfloat162float(__float2bfloat16_rn(v.x));
    float h1 = __bfloat162float(__float2bfloat16_rn(v.y));
    float h2 = __bfloat162float(__float2bfloat16_rn(v.z));
    float h3 = __bfloat162float(__float2bfloat16_rn(v.w));
    *(uint32_t*)&Hi[off]     = pack_bf16(h0, h1);
    *(uint32_t*)&Hi[off + 2] = pack_bf16(h2, h3);
    *(uint32_t*)&Lo[off]     = pack_bf16(v.x - h0, v.y - h1);
    *(uint32_t*)&Lo[off + 2] = pack_bf16(v.z - h2, v.w - h3);
}

__device__ __forceinline__ void f16_store4(uint16_t* Hi, int off, float4 v) {
    *(uint32_t*)&Hi[off]     = pack_f16(v.x, v.y);
    *(uint32_t*)&Hi[off + 2] = pack_f16(v.z, v.w);
}

#define MMA_BF16(d, a, b0, b1)                                              \
    asm volatile(                                                           \
        "mma.sync.aligned.m16n8k16.row.col.f32.bf16.bf16.f32 "              \
        "{%0,%1,%2,%3}, {%4,%5,%6,%7}, {%8,%9}, {%0,%1,%2,%3};"             \
        : "+f"(d[0]), "+f"(d[1]), "+f"(d[2]), "+f"(d[3])                    \
        : "r"(a[0]), "r"(a[1]), "r"(a[2]), "r"(a[3]), "r"(b0), "r"(b1))

#define MMA_F16(d, a, b0, b1)                                               \
    asm volatile(                                                           \
        "mma.sync.aligned.m16n8k16.row.col.f32.f16.f16.f32 "                \
        "{%0,%1,%2,%3}, {%4,%5,%6,%7}, {%8,%9}, {%0,%1,%2,%3};"             \
        : "+f"(d[0]), "+f"(d[1]), "+f"(d[2]), "+f"(d[3])                    \
        : "r"(a[0]), "r"(a[1]), "r"(a[2]), "r"(a[3]), "r"(b0), "r"(b1))

#define LDSM_X4(r, addr)                                                    \
    asm volatile("ldmatrix.sync.aligned.m8n8.x4.shared.b16 {%0,%1,%2,%3}, [%4];" \
        : "=r"(r[0]), "=r"(r[1]), "=r"(r[2]), "=r"(r[3]) : "r"(addr))

#define LDSM_X4_T(r, addr)                                                  \
    asm volatile("ldmatrix.sync.aligned.m8n8.x4.trans.shared.b16 {%0,%1,%2,%3}, [%4];" \
        : "=r"(r[0]), "=r"(r[1]), "=r"(r[2]), "=r"(r[3]) : "r"(addr))

#define CP_ASYNC16(dst, src)                                                \
    asm volatile("cp.async.cg.shared.global [%0], [%1], 16;" :: "r"(dst), "l"(src))
#define CP_COMMIT  asm volatile("cp.async.commit_group;")
#define CP_WAIT0   asm volatile("cp.async.wait_group 0;")
#define CP_WAIT1   asm volatile("cp.async.wait_group 1;")

// ---------------- weight pre-split kernels ----------------
__global__ __launch_bounds__(256) void wsplit_f16_kernel(
    const float* __restrict__ src, uint16_t* __restrict__ hi,
    uint16_t* __restrict__ lo, int n4)
{
    int i = blockIdx.x * 256 + threadIdx.x;
    if (i >= n4) return;
    float4 v = ((const float4*)src)[i];
    float h0 = __half2float(__float2half_rn(v.x));
    float h1 = __half2float(__float2half_rn(v.y));
    float h2 = __half2float(__float2half_rn(v.z));
    float h3 = __half2float(__float2half_rn(v.w));
    ((uint2*)hi)[i] = make_uint2(pack_f16(h0, h1), pack_f16(h2, h3));
    ((uint2*)lo)[i] = make_uint2(pack_f16(v.x - h0, v.y - h1),
                                 pack_f16(v.z - h2, v.w - h3));
}

__global__ __launch_bounds__(256) void wsplit_bf16_kernel(
    const float* __restrict__ src, uint16_t* __restrict__ hi,
    uint16_t* __restrict__ lo, int n4)
{
    int i = blockIdx.x * 256 + threadIdx.x;
    if (i >= n4) return;
    float4 v = ((const float4*)src)[i];
    float h0 = __bfloat162float(__float2bfloat16_rn(v.x));
    float h1 = __bfloat162float(__float2bfloat16_rn(v.y));
    float h2 = __bfloat162float(__float2bfloat16_rn(v.z));
    float h3 = __bfloat162float(__float2bfloat16_rn(v.w));
    ((uint2*)hi)[i] = make_uint2(pack_bf16(h0, h1), pack_bf16(h2, h3));
    ((uint2*)lo)[i] = make_uint2(pack_bf16(v.x - h0, v.y - h1),
                                 pack_bf16(v.z - h2, v.w - h3));
}

// ====== tensor-core embed: H = x[4096,64] @ EW[64,1024] + b + pe ======
#define ESTR_A 72
#define ESTR_B 136
#define EMB_SMEM_BYTES ((2 * 128 * ESTR_A + 2 * 64 * ESTR_B) * 2)  // 71680

__global__ __launch_bounds__(256) void embed_tc_kernel(
    const float* __restrict__ X,
    const uint16_t* __restrict__ EWhi, const uint16_t* __restrict__ EWlo,
    const float* __restrict__ b, const float* __restrict__ pe,
    float* __restrict__ H)
{
    extern __shared__ __align__(16) uint16_t esm[];
    uint16_t* Ahi = esm;
    uint16_t* Alo = esm + 128 * ESTR_A;
    uint16_t* Bhi = esm + 2 * 128 * ESTR_A;
    uint16_t* Blo = Bhi + 64 * ESTR_B;

    const int tid = threadIdx.x, lane = tid & 31, wid = tid >> 5;
    const int wm = wid & 3, wn = wid >> 2;
    const int bm = blockIdx.y * 128, bn = blockIdx.x * 128;

    // load x tile (128 x 64) split bf16
    #pragma unroll
    for (int i = 0; i < 8; i++) {
        int idx = i * 256 + tid;
        int r = idx >> 4, c4 = (idx & 15) * 4;
        float4 v = *(const float4*)&X[(size_t)(bm + r) * 64 + c4];
        split_store4(Ahi, Alo, r * ESTR_A + c4, v);
    }
    // load EW slice (64 x 128) hi/lo
    #pragma unroll
    for (int i = 0; i < 4; i++) {
        int idx = i * 256 + tid;
        int r = idx >> 4, c8 = (idx & 15) * 8;
        *(uint4*)&Bhi[r * ESTR_B + c8] = *(const uint4*)&EWhi[(size_t)r * EMBED + bn + c8];
        *(uint4*)&Blo[r * ESTR_B + c8] = *(const uint4*)&EWlo[(size_t)r * EMBED + bn + c8];
    }
    __syncthreads();

    const uint32_t sAhi = (uint32_t)__cvta_generic_to_shared(Ahi);
    const uint32_t sAlo = (uint32_t)__cvta_generic_to_shared(Alo);
    const uint32_t sBhi = (uint32_t)__cvta_generic_to_shared(Bhi);
    const uint32_t sBlo = (uint32_t)__cvta_generic_to_shared(Blo);

    const int a_row = wm * 32 + (lane & 15);
    const int a_koff = ((lane >> 4) & 1) * 8;
    const int b_krow = lane & 15;
    const int b_coff = wn * 64 + ((lane >> 4) & 1) * 8;

    float acc[2][8][4];
    #pragma unroll
    for (int m = 0; m < 2; m++)
        #pragma unroll
        for (int n = 0; n < 8; n++)
            #pragma unroll
            for (int c = 0; c < 4; c++) acc[m][n][c] = 0.f;

    #pragma unroll
    for (int c = 0; c < 4; c++) {     // K = 64 -> 4 k16 steps
        uint32_t ah[2][4], al[2][4];
        #pragma unroll
        for (int m = 0; m < 2; m++) {
            uint32_t off = (uint32_t)((a_row + m * 16) * ESTR_A + c * 16 + a_koff) * 2;
            LDSM_X4(ah[m], sAhi + off);
            LDSM_X4(al[m], sAlo + off);
        }
        #pragma unroll
        for (int j = 0; j < 4; j++) {
            uint32_t bh[4], bl[4];
            uint32_t off = (uint32_t)((c * 16 + b_krow) * ESTR_B + b_coff + j * 16) * 2;
            LDSM_X4_T(bh, sBhi + off);
            LDSM_X4_T(bl, sBlo + off);
            #pragma unroll
            for (int m = 0; m < 2; m++)
                #pragma unroll
                for (int t = 0; t < 2; t++) {
                    int n = j * 2 + t;
                    MMA_BF16(acc[m][n], ah[m], bh[2*t], bh[2*t+1]);
                    MMA_BF16(acc[m][n], ah[m], bl[2*t], bl[2*t+1]);
                    MMA_BF16(acc[m][n], al[m], bh[2*t], bh[2*t+1]);
                }
        }
    }

    #pragma unroll
    for (int m = 0; m < 2; m++) {
        int row0 = bm + wm * 32 + m * 16 + (lane >> 2);
        int s0r = row0 & (SEQ - 1);
        int s1r = (row0 + 8) & (SEQ - 1);
        #pragma unroll
        for (int n = 0; n < 8; n++) {
            int col = bn + wn * 64 + n * 8 + (lane & 3) * 2;
            float bx = b[col], by = b[col + 1];
            float2 v0, v1;
            v0.x = acc[m][n][0] + bx + pe[(size_t)s0r * EMBED + col];
            v0.y = acc[m][n][1] + by + pe[(size_t)s0r * EMBED + col + 1];
            v1.x = acc[m][n][2] + bx + pe[(size_t)s1r * EMBED + col];
            v1.y = acc[m][n][3] + by + pe[(size_t)s1r * EMBED + col + 1];
            *(float2*)&H[(size_t)row0 * EMBED + col]       = v0;
            *(float2*)&H[(size_t)(row0 + 8) * EMBED + col] = v1;
        }
    }
}

// ======== tensor-core QKV -> bf16 hi/lo outputs (Q pre-scaled 1/32) ========
// Epilogue stages results in smem (A-tile area) for coalesced 16B writeback.
#define QSTR 72
#define QKV_W_OFF    (2 * 128 * QSTR)
#define QKV_SMEM_BYTES ((2 * 128 * QSTR + 6 * 64 * QSTR) * 2)

__global__ __launch_bounds__(256) void qkv_tc_kernel(
    const float* __restrict__ H,
    const float* __restrict__ Wq, const float* __restrict__ Wk,
    const float* __restrict__ Wv,
    uint16_t* __restrict__ Qhi, uint16_t* __restrict__ Qlo,
    uint16_t* __restrict__ Khi, uint16_t* __restrict__ Klo,
    uint16_t* __restrict__ Vhi, uint16_t* __restrict__ Vlo)
{
    extern __shared__ __align__(16) uint16_t qsm[];
    uint16_t* Ahi = qsm;
    uint16_t* Alo = qsm + 128 * QSTR;
    uint16_t* Wb  = qsm + QKV_W_OFF;
    uint16_t* SHi = qsm;              // staging (reuses A area after frag load)
    uint16_t* SLo = qsm + 128 * 64;

    const int tid = threadIdx.x, lane = tid & 31, w = tid >> 5;
    const int t0 = blockIdx.x * 8;

    #pragma unroll
    for (int i = 0; i < 8; i++) {
        int idx = i * 256 + tid;
        int row = idx >> 4, c4 = (idx & 15) * 4;
        float4 v = *(const float4*)&H[(size_t)(t0 + (row >> 4)) * EMBED
                                      + (row & 15) * 64 + c4];
        split_store4(Ahi, Alo, row * QSTR + c4, v);
    }
    #pragma unroll
    for (int i = 0; i < 12; i++) {
        int idx = i * 256 + tid;
        int which = idx >> 10;
        int rem = idx & 1023;
        int row = rem >> 4, c4 = (rem & 15) * 4;
        const float* Wp = (which == 0) ? Wq : (which == 1) ? Wk : Wv;
        float4 v = *(const float4*)&Wp[row * 64 + c4];
        uint16_t* hi = Wb + which * 2 * 64 * QSTR;
        uint16_t* lo = hi + 64 * QSTR;
        split_store4(hi, lo, row * QSTR + c4, v);
    }
    __syncthreads();

    const uint32_t sA  = (uint32_t)__cvta_generic_to_shared(Ahi);
    const uint32_t sAl = (uint32_t)__cvta_generic_to_shared(Alo);
    const uint32_t sW  = (uint32_t)__cvta_generic_to_shared(Wb);

    uint32_t ah[4][4], al[4][4];
    {
        int arow = w * 16 + (lane & 15);
        int aoff = ((lane >> 4) & 1) * 8;
        #pragma unroll
        for (int c = 0; c < 4; c++) {
            uint32_t off = (uint32_t)(arow * QSTR + c * 16 + aoff) * 2;
            LDSM_X4(ah[c], sA + off);
            LDSM_X4(al[c], sAl + off);
        }
    }
    __syncthreads();   // all A frags in registers; A area now free for staging

    const int b_krow = lane & 15;
    const int b_coff = ((lane >> 4) & 1) * 8;

    const int ra = w * 16 + (lane >> 2);     // staging rows
    const int rb = ra + 8;
    const int cbase = (lane & 3) * 2;
    const int nn = (t0 >> 11);               // batch index (uniform in block)

    uint16_t* outs_hi[3] = {Qhi, Khi, Vhi};
    uint16_t* outs_lo[3] = {Qlo, Klo, Vlo};
    #pragma unroll
    for (int mat = 0; mat < 3; mat++) {
        const uint32_t bh_base = sW + (uint32_t)(mat * 2 * 64 * QSTR) * 2;
        const uint32_t bl_base = bh_base + (uint32_t)(64 * QSTR) * 2;

        float acc[8][4];
        #pragma unroll
        for (int j = 0; j < 8; j++)
            #pragma unroll
            for (int c = 0; c < 4; c++) acc[j][c] = 0.f;

        #pragma unroll
        for (int c = 0; c < 4; c++) {
            #pragma unroll
            for (int j2 = 0; j2 < 4; j2++) {
                uint32_t bh[4], bl[4];
                uint32_t off = (uint32_t)((c * 16 + b_krow) * QSTR + j2 * 16 + b_coff) * 2;
                LDSM_X4_T(bh, bh_base + off);
                LDSM_X4_T(bl, bl_base + off);
                #pragma unroll
                for (int t = 0; t < 2; t++) {
                    int j = j2 * 2 + t;
                    MMA_BF16(acc[j], ah[c], bh[2*t], bh[2*t+1]);
                    MMA_BF16(acc[j], ah[c], bl[2*t], bl[2*t+1]);
                    MMA_BF16(acc[j], al[c], bh[2*t], bh[2*t+1]);
                }
            }
        }

        // stage split results in smem
        const float scale = (mat == 0) ? 0.03125f : 1.0f;
        #pragma unroll
        for (int j = 0; j < 8; j++) {
            uint32_t hi0, lo0, hi1, lo1;
            split2(acc[j][0] * scale, acc[j][1] * scale, hi0, lo0);
            split2(acc[j][2] * scale, acc[j][3] * scale, hi1, lo1);
            *(uint32_t*)&SHi[ra * 64 + j * 8 + cbase] = hi0;
            *(uint32_t*)&SLo[ra * 64 + j * 8 + cbase] = lo0;
            *(uint32_t*)&SHi[rb * 64 + j * 8 + cbase] = hi1;
            *(uint32_t*)&SLo[rb * 64 + j * 8 + cbase] = lo1;
        }
        __syncthreads();

        // coalesced writeback: 128 rows x 64 cols, 16B chunks
        uint16_t* Ohi = outs_hi[mat];
        uint16_t* Olo = outs_lo[mat];
        #pragma unroll
        for (int i = 0; i < 4; i++) {
            int idx = i * 256 + tid;             // 0..1023
            int r = idx >> 3, c8 = (idx & 7) * 8;
            int tok = t0 + (r >> 4), head = r & 15;
            int s = tok & (SEQ - 1);
            size_t dst = ((size_t)(nn * HEADS + head) * SEQ + s) * HDIM + c8;
            *(uint4*)&Ohi[dst] = *(const uint4*)&SHi[r * 64 + c8];
            *(uint4*)&Olo[dst] = *(const uint4*)&SLo[r * 64 + c8];
        }
        __syncthreads();                          // staging reused next mat
    }
}

// ===== tensor-core flash attention: bf16 hi/lo K/V streamed via cp.async ====
#define ASTR 72
#define KVSTG (4 * 64 * ASTR)                 // elems per K/V stage
#define ATT_SMEM_BYTES (2 * KVSTG * 2)        // 73728 B

__global__ __launch_bounds__(256, 1) void attn_tc_kernel(
    const uint16_t* __restrict__ Qhi_g, const uint16_t* __restrict__ Qlo_g,
    const uint16_t* __restrict__ Khi_g, const uint16_t* __restrict__ Klo_g,
    const uint16_t* __restrict__ Vhi_g, const uint16_t* __restrict__ Vlo_g,
    float* __restrict__ O)
{
    extern __shared__ __align__(16) uint16_t asmm[];
    const int tid = threadIdx.x, lane = tid & 31, w = tid >> 5;
    const int nh = blockIdx.y;
    const int n = nh >> 4, h = nh & 15;
    const int q0blk = blockIdx.x * 128;

    const uint32_t s0 = (uint32_t)__cvta_generic_to_shared(asmm);
    const size_t nhbase = (size_t)nh * SEQ * HDIM;

    {
        #pragma unroll
        for (int i = 0; i < 8; i++) {
            int idx = i * 256 + tid;
            int t = idx >> 10, r = (idx >> 3) & 127, c = (idx & 7) * 8;
            const uint16_t* src = (t ? Qlo_g : Qhi_g)
                + nhbase + (size_t)(q0blk + r) * HDIM + c;
            uint32_t dst = s0 + (uint32_t)(KVSTG + t * 128 * ASTR + r * ASTR + c) * 2;
            CP_ASYNC16(dst, src);
        }
        CP_COMMIT;
    }
    const uint16_t* kvbase[4] = {Khi_g + nhbase, Klo_g + nhbase,
                                 Vhi_g + nhbase, Vlo_g + nhbase};
    {
        #pragma unroll
        for (int i = 0; i < 8; i++) {
            int idx = i * 256 + tid;
            int t = idx >> 9, r = (idx >> 3) & 63, c = (idx & 7) * 8;
            CP_ASYNC16(s0 + (uint32_t)(t * 64 * ASTR + r * ASTR + c) * 2,
                       kvbase[t] + (size_t)r * HDIM + c);
        }
        CP_COMMIT;
    }

    CP_WAIT1;
    __syncthreads();

    uint32_t aqh[4][4], aql[4][4];
    {
        int arow = w * 16 + (lane & 15);
        int aoff = ((lane >> 4) & 1) * 8;
        #pragma unroll
        for (int c = 0; c < 4; c++) {
            uint32_t off = (uint32_t)(KVSTG + arow * ASTR + c * 16 + aoff) * 2;
            LDSM_X4(aqh[c], s0 + off);
            LDSM_X4(aql[c], s0 + off + (uint32_t)(128 * ASTR) * 2);
        }
    }
    __syncthreads();

    float o[8][4];
    #pragma unroll
    for (int j = 0; j < 8; j++)
        #pragma unroll
        for (int c = 0; c < 4; c++) o[j][c] = 0.f;
    float m0 = -1e30f, m1 = -1e30f, l0 = 0.f, l1 = 0.f;

    const int kb_row = lane & 15;
    const int kb_col = ((lane >> 4) & 1) * 8;

    for (int kb = 0; kb < SEQ / 64; kb++) {
        const int cur = kb & 1;
        const bool more = (kb + 1 < SEQ / 64);

        if (more) {
            int nxt = cur ^ 1;
            size_t blk = (size_t)(kb + 1) * 64 * HDIM;
            #pragma unroll
            for (int i = 0; i < 8; i++) {
                int idx = i * 256 + tid;
                int t = idx >> 9, r = (idx >> 3) & 63, c = (idx & 7) * 8;
                CP_ASYNC16(s0 + (uint32_t)(nxt * KVSTG + t * 64 * ASTR + r * ASTR + c) * 2,
                           kvbase[t] + blk + (size_t)r * HDIM + c);
            }
            CP_COMMIT;
            CP_WAIT1;
        } else {
            CP_WAIT0;
        }
        __syncthreads();

        const uint32_t sKhi = s0 + (uint32_t)(cur * KVSTG) * 2;
        const uint32_t sKlo = sKhi + (uint32_t)(64 * ASTR) * 2;
        const uint32_t sVhi = sKhi + (uint32_t)(2 * 64 * ASTR) * 2;
        const uint32_t sVlo = sKhi + (uint32_t)(3 * 64 * ASTR) * 2;

        float s[8][4];
        #pragma unroll
        for (int j = 0; j < 8; j++)
            #pragma unroll
            for (int c = 0; c < 4; c++) s[j][c] = 0.f;

        #pragma unroll
        for (int c = 0; c < 4; c++) {
            #pragma unroll
            for (int j2 = 0; j2 < 4; j2++) {
                uint32_t kh[4], kl[4];
                uint32_t off = (uint32_t)((j2 * 16 + kb_row) * ASTR + c * 16 + kb_col) * 2;
                LDSM_X4(kh, sKhi + off);
                LDSM_X4(kl, sKlo + off);
                MMA_BF16(s[2*j2],   aqh[c], kh[0], kh[2]);
                MMA_BF16(s[2*j2],   aqh[c], kl[0], kl[2]);
                MMA_BF16(s[2*j2],   aql[c], kh[0], kh[2]);
                MMA_BF16(s[2*j2+1], aqh[c], kh[1], kh[3]);
                MMA_BF16(s[2*j2+1], aqh[c], kl[1], kl[3]);
                MMA_BF16(s[2*j2+1], aql[c], kh[1], kh[3]);
            }
        }

        float mx0 = -1e30f, mx1 = -1e30f;
        #pragma unroll
        for (int j = 0; j < 8; j++) {
            mx0 = fmaxf(mx0, fmaxf(s[j][0], s[j][1]));
            mx1 = fmaxf(mx1, fmaxf(s[j][2], s[j][3]));
        }
        mx0 = fmaxf(mx0, __shfl_xor_sync(0xffffffffu, mx0, 1));
        mx0 = fmaxf(mx0, __shfl_xor_sync(0xffffffffu, mx0, 2));
        mx1 = fmaxf(mx1, __shfl_xor_sync(0xffffffffu, mx1, 1));
        mx1 = fmaxf(mx1, __shfl_xor_sync(0xffffffffu, mx1, 2));
        float mn0 = fmaxf(m0, mx0), mn1 = fmaxf(m1, mx1);
        float corr0 = __expf(m0 - mn0), corr1 = __expf(m1 - mn1);
        m0 = mn0; m1 = mn1;

        float sum0 = 0.f, sum1 = 0.f;
        #pragma unroll
        for (int j = 0; j < 8; j++) {
            s[j][0] = __expf(s[j][0] - mn0); sum0 += s[j][0];
            s[j][1] = __expf(s[j][1] - mn0); sum0 += s[j][1];
            s[j][2] = __expf(s[j][2] - mn1); sum1 += s[j][2];
            s[j][3] = __expf(s[j][3] - mn1); sum1 += s[j][3];
        }
        sum0 += __shfl_xor_sync(0xffffffffu, sum0, 1);
        sum0 += __shfl_xor_sync(0xffffffffu, sum0, 2);
        sum1 += __shfl_xor_sync(0xffffffffu, sum1, 1);
        sum1 += __shfl_xor_sync(0xffffffffu, sum1, 2);
        l0 = l0 * corr0 + sum0;
        l1 = l1 * corr1 + sum1;

        #pragma unroll
        for (int j = 0; j < 8; j++) {
            o[j][0] *= corr0; o[j][1] *= corr0;
            o[j][2] *= corr1; o[j][3] *= corr1;
        }

        #pragma unroll
        for (int c = 0; c < 4; c++) {
            uint32_t ph[4], pl[4];
            split2(s[2*c][0],   s[2*c][1],   ph[0], pl[0]);
            split2(s[2*c][2],   s[2*c][3],   ph[1], pl[1]);
            split2(s[2*c+1][0], s[2*c+1][1], ph[2], pl[2]);
            split2(s[2*c+1][2], s[2*c+1][3], ph[3], pl[3]);
            #pragma unroll
            for (int j2 = 0; j2 < 4; j2++) {
                uint32_t vh[4], vl[4];
                uint32_t off = (uint32_t)((c * 16 + kb_row) * ASTR + j2 * 16 + kb_col) * 2;
                LDSM_X4_T(vh, sVhi + off);
                LDSM_X4_T(vl, sVlo + off);
                MMA_BF16(o[2*j2],   ph, vh[0], vh[1]);
                MMA_BF16(o[2*j2],   ph, vl[0], vl[1]);
                MMA_BF16(o[2*j2],   pl, vh[0], vh[1]);
                MMA_BF16(o[2*j2+1], ph, vh[2], vh[3]);
                MMA_BF16(o[2*j2+1], ph, vl[2], vl[3]);
                MMA_BF16(o[2*j2+1], pl, vh[2], vh[3]);
            }
        }
        __syncthreads();
    }

    float inv0 = 1.f / l0, inv1 = 1.f / l1;
    int qrow = q0blk + w * 16 + (lane >> 2);
    float* Ob0 = O + ((size_t)(n * SEQ) + qrow) * EMBED + h * 64 + (lane & 3) * 2;
    float* Ob1 = Ob0 + (size_t)8 * EMBED;
    #pragma unroll
    for (int j = 0; j < 8; j++) {
        *(float2*)&Ob0[j * 8] = make_float2(o[j][0] * inv0, o[j][1] * inv0);
        *(float2*)&Ob1[j * 8] = make_float2(o[j][2] * inv1, o[j][3] * inv1);
    }
}

// ==== tensor-core GEMM (R8-proven): A fp32 LDG+cvt, B cp.async fp16 hi/lo ====
#define GSTRIDE_A 40
#define GSTRIDE_B 136
#define ABUF (128 * GSTRIDE_A)
#define BBUF (32 * GSTRIDE_B)
#define GEMM_SMEM_BYTES ((2 * ABUF + 4 * BBUF) * 2)   // 55296

__global__ __launch_bounds__(256) void gemm_tc_f16(
    const float* __restrict__ A,
    const uint16_t* __restrict__ BHg, const uint16_t* __restrict__ BLg,
    const float* __restrict__ bias, float* __restrict__ C,
    int M, int N, int K, int relu)
{
    extern __shared__ __align__(16) uint16_t dsm[];
    const int tid  = threadIdx.x;
    const int lane = tid & 31;
    const int wid  = tid >> 5;
    const int wm   = wid & 3;
    const int wn   = wid >> 2;
    const int bm   = blockIdx.y * 128;
    const int bn   = blockIdx.x * 128;

    const int ar  = tid >> 3, ac4 = (tid & 7) * 4;
    const int br  = tid >> 4, bc8 = (tid & 15) * 8;

    float4 pa[4];
    const int nk = K >> 5;
    const uint32_t s0 = (uint32_t)__cvta_generic_to_shared(dsm);

    {
        uint32_t dhi = s0 + (uint32_t)(2 * ABUF + br * GSTRIDE_B + bc8) * 2;
        uint32_t dlo = dhi + BBUF * 2;
        #pragma unroll
        for (int i = 0; i < 2; i++) {
            CP_ASYNC16(dhi + i * 16 * GSTRIDE_B * 2, &BHg[(size_t)(br + i * 16) * N + bn + bc8]);
            CP_ASYNC16(dlo + i * 16 * GSTRIDE_B * 2, &BLg[(size_t)(br + i * 16) * N + bn + bc8]);
        }
        CP_COMMIT;
        #pragma unroll
        for (int i = 0; i < 4; i++)
            pa[i] = *(const float4*)&A[(size_t)(bm + ar + i * 32) * K + ac4];
        #pragma unroll
        for (int i = 0; i < 4; i++)
            f16_store4(dsm, (ar + i * 32) * GSTRIDE_A + ac4, pa[i]);
        CP_WAIT0;
    }
    __syncthreads();

    float acc[2][8][4];
    #pragma unroll
    for (int m = 0; m < 2; m++)
        #pragma unroll
        for (int n = 0; n < 8; n++)
            #pragma unroll
            for (int c = 0; c < 4; c++) acc[m][n][c] = 0.f;

    const int a_row = wm * 32 + (lane & 15);
    const int a_koff = ((lane >> 4) & 1) * 8;
    const int b_krow = (lane & 15);
    const int b_coff = wn * 64 + ((lane >> 4) & 1) * 8;

    for (int kb = 0; kb < nk; kb++) {
        const int cur = kb & 1, nxt = cur ^ 1;
        const bool more = (kb + 1 < nk);

        if (more) {
            int k0 = (kb + 1) * 32;
            uint32_t dhi = s0 + (uint32_t)(2 * ABUF + nxt * 2 * BBUF + br * GSTRIDE_B + bc8) * 2;
            uint32_t dlo = dhi + BBUF * 2;
            #pragma unroll
            for (int i = 0; i < 2; i++) {
                CP_ASYNC16(dhi + i * 16 * GSTRIDE_B * 2, &BHg[(size_t)(k0 + br + i * 16) * N + bn + bc8]);
                CP_ASYNC16(dlo + i * 16 * GSTRIDE_B * 2, &BLg[(size_t)(k0 + br + i * 16) * N + bn + bc8]);
            }
            CP_COMMIT;
            #pragma unroll
            for (int i = 0; i < 4; i++)
                pa[i] = *(const float4*)&A[(size_t)(bm + ar + i * 32) * K + k0 + ac4];
        }

        const uint32_t bA   = s0 + (uint32_t)(cur * ABUF) * 2;
        const uint32_t bBhi = s0 + (uint32_t)(2 * ABUF + cur * 2 * BBUF) * 2;
        const uint32_t bBlo = bBhi + BBUF * 2;

        #pragma unroll
        for (int ks = 0; ks < 32; ks += 16) {
            uint32_t ah[2][4], bh[4][4], bl[4][4];
            #pragma unroll
            for (int m = 0; m < 2; m++) {
                uint32_t off = ((a_row + m * 16) * GSTRIDE_A + ks + a_koff) * 2;
                LDSM_X4(ah[m], bA + off);
            }
            #pragma unroll
            for (int j = 0; j < 4; j++) {
                uint32_t off = ((ks + b_krow) * GSTRIDE_B + b_coff + j * 16) * 2;
                LDSM_X4_T(bh[j], bBhi + off);
                LDSM_X4_T(bl[j], bBlo + off);
            }
            #pragma unroll
            for (int m = 0; m < 2; m++)
                #pragma unroll
                for (int j = 0; j < 4; j++)
                    #pragma unroll
                    for (int t = 0; t < 2; t++) {
                        int n = j * 2 + t;
                        MMA_F16(acc[m][n], ah[m], bh[j][2*t], bh[j][2*t+1]);
                        MMA_F16(acc[m][n], ah[m], bl[j][2*t], bl[j][2*t+1]);
                    }
        }

        if (more) {
            uint16_t* Ah = dsm + nxt * ABUF;
            #pragma unroll
            for (int i = 0; i < 4; i++)
                f16_store4(Ah, (ar + i * 32) * GSTRIDE_A + ac4, pa[i]);
            CP_WAIT0;
            __syncthreads();
        }
    }

    #pragma unroll
    for (int m = 0; m < 2; m++) {
        int row0 = bm + wm * 32 + m * 16 + (lane >> 2);
        #pragma unroll
        for (int n = 0; n < 8; n++) {
            int col = bn + wn * 64 + n * 8 + (lane & 3) * 2;
            float bx = bias[col], by = bias[col + 1];
            float2 v0 = make_float2(acc[m][n][0] + bx, acc[m][n][1] + by);
            float2 v1 = make_float2(acc[m][n][2] + bx, acc[m][n][3] + by);
            if (relu) {
                v0.x = fmaxf(v0.x, 0.f); v0.y = fmaxf(v0.y, 0.f);
                v1.x = fmaxf(v1.x, 0.f); v1.y = fmaxf(v1.y, 0.f);
            }
            *(float2*)&C[(size_t)row0 * N + col]       = v0;
            *(float2*)&C[(size_t)(row0 + 8) * N + col] = v1;
        }
    }
}

// ---------------- LayerNorm(A + R) * g + b : one pass, reg-resident -------
__global__ __launch_bounds__(256) void ln_kernel(
    const float* __restrict__ A, const float* __restrict__ R,
    const float* __restrict__ g, const float* __restrict__ b,
    float* __restrict__ Out)
{
    const int token = blockIdx.x, tid = threadIdx.x;
    const int lane = tid & 31, wid = tid >> 5;
    __shared__ float rs[8], rq[8];

    const float4 a = ((const float4*)A)[(size_t)token * 256 + tid];
    const float4 r = ((const float4*)R)[(size_t)token * 256 + tid];
    float4 v = make_float4(a.x + r.x, a.y + r.y, a.z + r.z, a.w + r.w);

    float sum = v.x + v.y + v.z + v.w;
    float sq  = v.x * v.x + v.y * v.y + v.z * v.z + v.w * v.w;
    #pragma unroll
    for (int off = 16; off > 0; off >>= 1) {
        sum += __shfl_xor_sync(0xffffffffu, sum, off);
        sq  += __shfl_xor_sync(0xffffffffu, sq,  off);
    }
    if (lane == 0) { rs[wid] = sum; rq[wid] = sq; }
    __syncthreads();
    if (tid == 0) {
        float S = 0.f, Qs = 0.f;
        #pragma unroll
        for (int i = 0; i < 8; i++) { S += rs[i]; Qs += rq[i]; }
        rs[0] = S; rq[0] = Qs;
    }
    __syncthreads();
    const float mean = rs[0] * (1.f / EMBED);
    const float var  = rq[0] * (1.f / EMBED) - mean * mean;
    const float rstd = rsqrtf(var + 1e-5f);

    const float4 gv = ((const float4*)g)[tid];
    const float4 bv = ((const float4*)b)[tid];
    float4 o;
    o.x = (v.x - mean) * rstd * gv.x + bv.x;
    o.y = (v.y - mean) * rstd * gv.y + bv.y;
    o.z = (v.z - mean) * rstd * gv.z + bv.z;
    o.w = (v.w - mean) * rstd * gv.w + bv.w;
    ((float4*)Out)[(size_t)token * 256 + tid] = o;
}

// ---------------- launcher ----------------
extern "C" void kernel_launch(void* const* d_in, const int* in_sizes, int n_in,
                              void* d_out, int out_size)
{
    const float* x       = (const float*)d_in[0];
    const float* embed_W = (const float*)d_in[2];
    const float* embed_b = (const float*)d_in[3];
    const float* pe      = (const float*)d_in[4];
    const float* Wq      = (const float*)d_in[5];
    const float* Wk      = (const float*)d_in[6];
    const float* Wv      = (const float*)d_in[7];
    const float* Wo      = (const float*)d_in[8];
    const float* bo      = (const float*)d_in[9];
    const float* ln1_g   = (const float*)d_in[10];
    const float* ln1_b   = (const float*)d_in[11];
    const float* W1      = (const float*)d_in[12];
    const float* b1      = (const float*)d_in[13];
    const float* W2      = (const float*)d_in[14];
    const float* b2      = (const float*)d_in[15];
    const float* ln2_g   = (const float*)d_in[16];
    const float* ln2_b   = (const float*)d_in[17];

    static float *H = nullptr, *X1, *T, *O, *F;
    static uint16_t *Qhi, *Qlo, *Khi, *Klo, *Vhi, *Vlo;
    static uint16_t *WoHi, *WoLo, *W1Hi, *W1Lo, *W2Hi, *W2Lo, *EWHi, *EWLo;
    if (!H) {
        cudaGetSymbolAddress((void**)&H,  g_H);
        cudaGetSymbolAddress((void**)&X1, g_X1);
        cudaGetSymbolAddress((void**)&T,  g_T);
        cudaGetSymbolAddress((void**)&O,  g_O);
        cudaGetSymbolAddress((void**)&F,  g_F);
        cudaGetSymbolAddress((void**)&Qhi, g_Qhi);
        cudaGetSymbolAddress((void**)&Qlo, g_Qlo);
        cudaGetSymbolAddress((void**)&Khi, g_Khi);
        cudaGetSymbolAddress((void**)&Klo, g_Klo);
        cudaGetSymbolAddress((void**)&Vhi, g_Vhi);
        cudaGetSymbolAddress((void**)&Vlo, g_Vlo);
        cudaGetSymbolAddress((void**)&WoHi, g_WoHi);
        cudaGetSymbolAddress((void**)&WoLo, g_WoLo);
        cudaGetSymbolAddress((void**)&W1Hi, g_W1Hi);
        cudaGetSymbolAddress((void**)&W1Lo, g_W1Lo);
        cudaGetSymbolAddress((void**)&W2Hi, g_W2Hi);
        cudaGetSymbolAddress((void**)&W2Lo, g_W2Lo);
        cudaGetSymbolAddress((void**)&EWHi, g_EWHi);
        cudaGetSymbolAddress((void**)&EWLo, g_EWLo);
        cudaFuncSetAttribute(gemm_tc_f16,
            cudaFuncAttributeMaxDynamicSharedMemorySize, GEMM_SMEM_BYTES);
        cudaFuncSetAttribute(qkv_tc_kernel,
            cudaFuncAttributeMaxDynamicSharedMemorySize, QKV_SMEM_BYTES);
        cudaFuncSetAttribute(attn_tc_kernel,
            cudaFuncAttributeMaxDynamicSharedMemorySize, ATT_SMEM_BYTES);
        cudaFuncSetAttribute(embed_tc_kernel,
            cudaFuncAttributeMaxDynamicSharedMemorySize, EMB_SMEM_BYTES);
    }

    {
        int n4o = 3 * EMBED * EMBED / 4;
        int n4f = 3 * EMBED * FFN_DIM / 4;
        int n4e = 64 * EMBED / 4;
        wsplit_f16_kernel<<<(n4o + 255) / 256, 256>>>(Wo, WoHi, WoLo, n4o);
        wsplit_f16_kernel<<<(n4f + 255) / 256, 256>>>(W1, W1Hi, W1Lo, n4f);
        wsplit_f16_kernel<<<(n4f + 255) / 256, 256>>>(W2, W2Hi, W2Lo, n4f);
        wsplit_bf16_kernel<<<(n4e + 255) / 256, 256>>>(embed_W, EWHi, EWLo, n4e);
    }

    embed_tc_kernel<<<dim3(EMBED / 128, TOKENS / 128), 256, EMB_SMEM_BYTES>>>(
        x, EWHi, EWLo, embed_b, pe, H);

    for (int l = 0; l < 3; l++) {
        qkv_tc_kernel<<<TOKENS / 8, 256, QKV_SMEM_BYTES>>>(H,
            Wq + (size_t)l * HDIM * HDIM,
            Wk + (size_t)l * HDIM * HDIM,
            Wv + (size_t)l * HDIM * HDIM,
            Qhi, Qlo, Khi, Klo, Vhi, Vlo);

        attn_tc_kernel<<<dim3(SEQ / 128, BATCH * HEADS), 256, ATT_SMEM_BYTES>>>(
            Qhi, Qlo, Khi, Klo, Vhi, Vlo, O);

        gemm_tc_f16<<<dim3(EMBED / 128, TOKENS / 128), 256, GEMM_SMEM_BYTES>>>(
            O, WoHi + (size_t)l * EMBED * EMBED, WoLo + (size_t)l * EMBED * EMBED,
            bo + (size_t)l * EMBED, T, TOKENS, EMBED, EMBED, 0);

        ln_kernel<<<TOKENS, 256>>>(T, H,
            ln1_g + (size_t)l * EMBED, ln1_b + (size_t)l * EMBED, X1);

        gemm_tc_f16<<<dim3(FFN_DIM / 128, TOKENS / 128), 256, GEMM_SMEM_BYTES>>>(
            X1, W1Hi + (size_t)l * EMBED * FFN_DIM, W1Lo + (size_t)l * EMBED * FFN_DIM,
            b1 + (size_t)l * FFN_DIM, F, TOKENS, FFN_DIM, EMBED, 1);

        gemm_tc_f16<<<dim3(EMBED / 128, TOKENS / 128), 256, GEMM_SMEM_BYTES>>>(
            F, W2Hi + (size_t)l * FFN_DIM * EMBED, W2Lo + (size_t)l * FFN_DIM * EMBED,
            b2 + (size_t)l * EMBED, T, TOKENS, EMBED, FFN_DIM, 0);

        float* dst = (l == 2) ? (float*)d_out : H;
        ln_kernel<<<TOKENS, 256>>>(T, X1,
            ln2_g + (size_t)l * EMBED, ln2_b + (size_t)l * EMBED, dst);
    }
    (void)in_sizes; (void)n_in; (void)out_size;
}

// round 12
// speedup vs baseline: 1.3178x; 1.2787x over previous
#include <cuda_runtime.h>
#include <cuda_bf16.h>
#include <cuda_fp16.h>
#include <cstdint>

#define BATCH   2
#define SEQ     2048
#define EMBED   1024
#define HEADS   16
#define HDIM    64
#define FFN_DIM 4096
#define TOKENS  (BATCH * SEQ)

// ---------------- scratch (no allocations allowed) ----------------
__device__ float g_H [TOKENS * EMBED];
__device__ float g_X1[TOKENS * EMBED];
__device__ float g_T [TOKENS * EMBED];
__device__ float g_O [TOKENS * EMBED];
__device__ float g_F [TOKENS * FFN_DIM];
// bf16 hi/lo QKV, layout [n][h][s][d]; Q pre-scaled by 1/32
__device__ uint16_t g_Qhi[TOKENS * EMBED];
__device__ uint16_t g_Qlo[TOKENS * EMBED];
__device__ uint16_t g_Khi[TOKENS * EMBED];
__device__ uint16_t g_Klo[TOKENS * EMBED];
__device__ uint16_t g_Vhi[TOKENS * EMBED];
__device__ uint16_t g_Vlo[TOKENS * EMBED];

// single-fp16 weight copies (per layer, contiguous)
__device__ uint16_t g_WoH[3 * EMBED * EMBED];
__device__ uint16_t g_W1H[3 * EMBED * FFN_DIM];
__device__ uint16_t g_W2H[3 * FFN_DIM * EMBED];
// pre-split bf16 hi/lo embed weight
__device__ uint16_t g_EWHi[INT32_C(64) * EMBED];
__device__ uint16_t g_EWLo[INT32_C(64) * EMBED];

// ---------------- common helpers ----------------
__device__ __forceinline__ uint32_t pack_bf16(float x, float y) {
    __nv_bfloat162 h = __floats2bfloat162_rn(x, y);
    return *reinterpret_cast<uint32_t*>(&h);
}
__device__ __forceinline__ uint32_t pack_f16(float x, float y) {
    __half2 h = __floats2half2_rn(x, y);
    return *reinterpret_cast<uint32_t*>(&h);
}

__device__ __forceinline__ void split2(float x, float y, uint32_t& hi, uint32_t& lo) {
    float hx = __bfloat162float(__float2bfloat16_rn(x));
    float hy = __bfloat162float(__float2bfloat16_rn(y));
    hi = pack_bf16(hx, hy);
    lo = pack_bf16(x - hx, y - hy);
}

__device__ __forceinline__ void split_store4(uint16_t* Hi, uint16_t* Lo, int off, float4 v) {
    float h0 = __bfloat162float(__float2bfloat16_rn(v.x));
    float h1 = __bfloat162float(__float2bfloat16_rn(v.y));
    float h2 = __bfloat162float(__float2bfloat16_rn(v.z));
    float h3 = __bfloat162float(__float2bfloat16_rn(v.w));
    *(uint32_t*)&Hi[off]     = pack_bf16(h0, h1);
    *(uint32_t*)&Hi[off + 2] = pack_bf16(h2, h3);
    *(uint32_t*)&Lo[off]     = pack_bf16(v.x - h0, v.y - h1);
    *(uint32_t*)&Lo[off + 2] = pack_bf16(v.z - h2, v.w - h3);
}

__device__ __forceinline__ void f16_store4(uint16_t* Hi, int off, float4 v) {
    *(uint32_t*)&Hi[off]     = pack_f16(v.x, v.y);
    *(uint32_t*)&Hi[off + 2] = pack_f16(v.z, v.w);
}

#define MMA_BF16(d, a, b0, b1)                                              \
    asm volatile(                                                           \
        "mma.sync.aligned.m16n8k16.row.col.f32.bf16.bf16.f32 "              \
        "{%0,%1,%2,%3}, {%4,%5,%6,%7}, {%8,%9}, {%0,%1,%2,%3};"             \
        : "+f"(d[0]), "+f"(d[1]), "+f"(d[2]), "+f"(d[3])                    \
        : "r"(a[0]), "r"(a[1]), "r"(a[2]), "r"(a[3]), "r"(b0), "r"(b1))

#define MMA_F16(d, a, b0, b1)                                               \
    asm volatile(                                                           \
        "mma.sync.aligned.m16n8k16.row.col.f32.f16.f16.f32 "                \
        "{%0,%1,%2,%3}, {%4,%5,%6,%7}, {%8,%9}, {%0,%1,%2,%3};"             \
        : "+f"(d[0]), "+f"(d[1]), "+f"(d[2]), "+f"(d[3])                    \
        : "r"(a[0]), "r"(a[1]), "r"(a[2]), "r"(a[3]), "r"(b0), "r"(b1))

#define LDSM_X4(r, addr)                                                    \
    asm volatile("ldmatrix.sync.aligned.m8n8.x4.shared.b16 {%0,%1,%2,%3}, [%4];" \
        : "=r"(r[0]), "=r"(r[1]), "=r"(r[2]), "=r"(r[3]) : "r"(addr))

#define LDSM_X4_T(r, addr)                                                  \
    asm volatile("ldmatrix.sync.aligned.m8n8.x4.trans.shared.b16 {%0,%1,%2,%3}, [%4];" \
        : "=r"(r[0]), "=r"(r[1]), "=r"(r[2]), "=r"(r[3]) : "r"(addr))

#define CP_ASYNC16(dst, src)                                                \
    asm volatile("cp.async.cg.shared.global [%0], [%1], 16;" :: "r"(dst), "l"(src))
#define CP_COMMIT  asm volatile("cp.async.commit_group;")
#define CP_WAIT0   asm volatile("cp.async.wait_group 0;")
#define CP_WAIT1   asm volatile("cp.async.wait_group 1;")

// ---------------- weight convert: fp32 -> single fp16 ----------------
__global__ __launch_bounds__(256) void wconv_f16_kernel(
    const float* __restrict__ src, uint16_t* __restrict__ hi, int n4)
{
    int i = blockIdx.x * 256 + threadIdx.x;
    if (i >= n4) return;
    float4 v = ((const float4*)src)[i];
    ((uint2*)hi)[i] = make_uint2(pack_f16(v.x, v.y), pack_f16(v.z, v.w));
}

__global__ __launch_bounds__(256) void wsplit_bf16_kernel(
    const float* __restrict__ src, uint16_t* __restrict__ hi,
    uint16_t* __restrict__ lo, int n4)
{
    int i = blockIdx.x * 256 + threadIdx.x;
    if (i >= n4) return;
    float4 v = ((const float4*)src)[i];
    float h0 = __bfloat162float(__float2bfloat16_rn(v.x));
    float h1 = __bfloat162float(__float2bfloat16_rn(v.y));
    float h2 = __bfloat162float(__float2bfloat16_rn(v.z));
    float h3 = __bfloat162float(__float2bfloat16_rn(v.w));
    ((uint2*)hi)[i] = make_uint2(pack_bf16(h0, h1), pack_bf16(h2, h3));
    ((uint2*)lo)[i] = make_uint2(pack_bf16(v.x - h0, v.y - h1),
                                 pack_bf16(v.z - h2, v.w - h3));
}

// ====== tensor-core embed: H = x[4096,64] @ EW[64,1024] + b + pe ======
#define ESTR_A 72
#define ESTR_B 136
#define EMB_SMEM_BYTES ((2 * 128 * ESTR_A + 2 * 64 * ESTR_B) * 2)  // 71680

__global__ __launch_bounds__(256) void embed_tc_kernel(
    const float* __restrict__ X,
    const uint16_t* __restrict__ EWhi, const uint16_t* __restrict__ EWlo,
    const float* __restrict__ b, const float* __restrict__ pe,
    float* __restrict__ H)
{
    extern __shared__ __align__(16) uint16_t esm[];
    uint16_t* Ahi = esm;
    uint16_t* Alo = esm + 128 * ESTR_A;
    uint16_t* Bhi = esm + 2 * 128 * ESTR_A;
    uint16_t* Blo = Bhi + 64 * ESTR_B;

    const int tid = threadIdx.x, lane = tid & 31, wid = tid >> 5;
    const int wm = wid & 3, wn = wid >> 2;
    const int bm = blockIdx.y * 128, bn = blockIdx.x * 128;

    #pragma unroll
    for (int i = 0; i < 8; i++) {
        int idx = i * 256 + tid;
        int r = idx >> 4, c4 = (idx & 15) * 4;
        float4 v = *(const float4*)&X[(size_t)(bm + r) * 64 + c4];
        split_store4(Ahi, Alo, r * ESTR_A + c4, v);
    }
    #pragma unroll
    for (int i = 0; i < 4; i++) {
        int idx = i * 256 + tid;
        int r = idx >> 4, c8 = (idx & 15) * 8;
        *(uint4*)&Bhi[r * ESTR_B + c8] = *(const uint4*)&EWhi[(size_t)r * EMBED + bn + c8];
        *(uint4*)&Blo[r * ESTR_B + c8] = *(const uint4*)&EWlo[(size_t)r * EMBED + bn + c8];
    }
    __syncthreads();

    const uint32_t sAhi = (uint32_t)__cvta_generic_to_shared(Ahi);
    const uint32_t sAlo = (uint32_t)__cvta_generic_to_shared(Alo);
    const uint32_t sBhi = (uint32_t)__cvta_generic_to_shared(Bhi);
    const uint32_t sBlo = (uint32_t)__cvta_generic_to_shared(Blo);

    const int a_row = wm * 32 + (lane & 15);
    const int a_koff = ((lane >> 4) & 1) * 8;
    const int b_krow = lane & 15;
    const int b_coff = wn * 64 + ((lane >> 4) & 1) * 8;

    float acc[2][8][4];
    #pragma unroll
    for (int m = 0; m < 2; m++)
        #pragma unroll
        for (int n = 0; n < 8; n++)
            #pragma unroll
            for (int c = 0; c < 4; c++) acc[m][n][c] = 0.f;

    #pragma unroll
    for (int c = 0; c < 4; c++) {
        uint32_t ah[2][4], al[2][4];
        #pragma unroll
        for (int m = 0; m < 2; m++) {
            uint32_t off = (uint32_t)((a_row + m * 16) * ESTR_A + c * 16 + a_koff) * 2;
            LDSM_X4(ah[m], sAhi + off);
            LDSM_X4(al[m], sAlo + off);
        }
        #pragma unroll
        for (int j = 0; j < 4; j++) {
            uint32_t bh[4], bl[4];
            uint32_t off = (uint32_t)((c * 16 + b_krow) * ESTR_B + b_coff + j * 16) * 2;
            LDSM_X4_T(bh, sBhi + off);
            LDSM_X4_T(bl, sBlo + off);
            #pragma unroll
            for (int m = 0; m < 2; m++)
                #pragma unroll
                for (int t = 0; t < 2; t++) {
                    int n = j * 2 + t;
                    MMA_BF16(acc[m][n], ah[m], bh[2*t], bh[2*t+1]);
                    MMA_BF16(acc[m][n], ah[m], bl[2*t], bl[2*t+1]);
                    MMA_BF16(acc[m][n], al[m], bh[2*t], bh[2*t+1]);
                }
        }
    }

    #pragma unroll
    for (int m = 0; m < 2; m++) {
        int row0 = bm + wm * 32 + m * 16 + (lane >> 2);
        int s0r = row0 & (SEQ - 1);
        int s1r = (row0 + 8) & (SEQ - 1);
        #pragma unroll
        for (int n = 0; n < 8; n++) {
            int col = bn + wn * 64 + n * 8 + (lane & 3) * 2;
            float bx = b[col], by = b[col + 1];
            float2 v0, v1;
            v0.x = acc[m][n][0] + bx + pe[(size_t)s0r * EMBED + col];
            v0.y = acc[m][n][1] + by + pe[(size_t)s0r * EMBED + col + 1];
            v1.x = acc[m][n][2] + bx + pe[(size_t)s1r * EMBED + col];
            v1.y = acc[m][n][3] + by + pe[(size_t)s1r * EMBED + col + 1];
            *(float2*)&H[(size_t)row0 * EMBED + col]       = v0;
            *(float2*)&H[(size_t)(row0 + 8) * EMBED + col] = v1;
        }
    }
}

// ======== tensor-core QKV -> bf16 hi/lo outputs (Q pre-scaled 1/32) ========
#define QSTR 72
#define QKV_W_OFF    (2 * 128 * QSTR)
#define QKV_SMEM_BYTES ((2 * 128 * QSTR + 6 * 64 * QSTR) * 2)

__global__ __launch_bounds__(256) void qkv_tc_kernel(
    const float* __restrict__ H,
    const float* __restrict__ Wq, const float* __restrict__ Wk,
    const float* __restrict__ Wv,
    uint16_t* __restrict__ Qhi, uint16_t* __restrict__ Qlo,
    uint16_t* __restrict__ Khi, uint16_t* __restrict__ Klo,
    uint16_t* __restrict__ Vhi, uint16_t* __restrict__ Vlo)
{
    extern __shared__ __align__(16) uint16_t qsm[];
    uint16_t* Ahi = qsm;
    uint16_t* Alo = qsm + 128 * QSTR;
    uint16_t* Wb  = qsm + QKV_W_OFF;
    uint16_t* SHi = qsm;
    uint16_t* SLo = qsm + 128 * 64;

    const int tid = threadIdx.x, lane = tid & 31, w = tid >> 5;
    const int t0 = blockIdx.x * 8;

    #pragma unroll
    for (int i = 0; i < 8; i++) {
        int idx = i * 256 + tid;
        int row = idx >> 4, c4 = (idx & 15) * 4;
        float4 v = *(const float4*)&H[(size_t)(t0 + (row >> 4)) * EMBED
                                      + (row & 15) * 64 + c4];
        split_store4(Ahi, Alo, row * QSTR + c4, v);
    }
    #pragma unroll
    for (int i = 0; i < 12; i++) {
        int idx = i * 256 + tid;
        int which = idx >> 10;
        int rem = idx & 1023;
        int row = rem >> 4, c4 = (rem & 15) * 4;
        const float* Wp = (which == 0) ? Wq : (which == 1) ? Wk : Wv;
        float4 v = *(const float4*)&Wp[row * 64 + c4];
        uint16_t* hi = Wb + which * 2 * 64 * QSTR;
        uint16_t* lo = hi + 64 * QSTR;
        split_store4(hi, lo, row * QSTR + c4, v);
    }
    __syncthreads();

    const uint32_t sA  = (uint32_t)__cvta_generic_to_shared(Ahi);
    const uint32_t sAl = (uint32_t)__cvta_generic_to_shared(Alo);
    const uint32_t sW  = (uint32_t)__cvta_generic_to_shared(Wb);

    uint32_t ah[4][4], al[4][4];
    {
        int arow = w * 16 + (lane & 15);
        int aoff = ((lane >> 4) & 1) * 8;
        #pragma unroll
        for (int c = 0; c < 4; c++) {
            uint32_t off = (uint32_t)(arow * QSTR + c * 16 + aoff) * 2;
            LDSM_X4(ah[c], sA + off);
            LDSM_X4(al[c], sAl + off);
        }
    }
    __syncthreads();

    const int b_krow = lane & 15;
    const int b_coff = ((lane >> 4) & 1) * 8;

    const int ra = w * 16 + (lane >> 2);
    const int rb = ra + 8;
    const int cbase = (lane & 3) * 2;
    const int nn = (t0 >> 11);

    uint16_t* outs_hi[3] = {Qhi, Khi, Vhi};
    uint16_t* outs_lo[3] = {Qlo, Klo, Vlo};
    #pragma unroll
    for (int mat = 0; mat < 3; mat++) {
        const uint32_t bh_base = sW + (uint32_t)(mat * 2 * 64 * QSTR) * 2;
        const uint32_t bl_base = bh_base + (uint32_t)(64 * QSTR) * 2;

        float acc[8][4];
        #pragma unroll
        for (int j = 0; j < 8; j++)
            #pragma unroll
            for (int c = 0; c < 4; c++) acc[j][c] = 0.f;

        #pragma unroll
        for (int c = 0; c < 4; c++) {
            #pragma unroll
            for (int j2 = 0; j2 < 4; j2++) {
                uint32_t bh[4], bl[4];
                uint32_t off = (uint32_t)((c * 16 + b_krow) * QSTR + j2 * 16 + b_coff) * 2;
                LDSM_X4_T(bh, bh_base + off);
                LDSM_X4_T(bl, bl_base + off);
                #pragma unroll
                for (int t = 0; t < 2; t++) {
                    int j = j2 * 2 + t;
                    MMA_BF16(acc[j], ah[c], bh[2*t], bh[2*t+1]);
                    MMA_BF16(acc[j], ah[c], bl[2*t], bl[2*t+1]);
                    MMA_BF16(acc[j], al[c], bh[2*t], bh[2*t+1]);
                }
            }
        }

        const float scale = (mat == 0) ? 0.03125f : 1.0f;
        #pragma unroll
        for (int j = 0; j < 8; j++) {
            uint32_t hi0, lo0, hi1, lo1;
            split2(acc[j][0] * scale, acc[j][1] * scale, hi0, lo0);
            split2(acc[j][2] * scale, acc[j][3] * scale, hi1, lo1);
            *(uint32_t*)&SHi[ra * 64 + j * 8 + cbase] = hi0;
            *(uint32_t*)&SLo[ra * 64 + j * 8 + cbase] = lo0;
            *(uint32_t*)&SHi[rb * 64 + j * 8 + cbase] = hi1;
            *(uint32_t*)&SLo[rb * 64 + j * 8 + cbase] = lo1;
        }
        __syncthreads();

        uint16_t* Ohi = outs_hi[mat];
        uint16_t* Olo = outs_lo[mat];
        #pragma unroll
        for (int i = 0; i < 4; i++) {
            int idx = i * 256 + tid;
            int r = idx >> 3, c8 = (idx & 7) * 8;
            int tok = t0 + (r >> 4), head = r & 15;
            int s = tok & (SEQ - 1);
            size_t dst = ((size_t)(nn * HEADS + head) * SEQ + s) * HDIM + c8;
            *(uint4*)&Ohi[dst] = *(const uint4*)&SHi[r * 64 + c8];
            *(uint4*)&Olo[dst] = *(const uint4*)&SLo[r * 64 + c8];
        }
        __syncthreads();
    }
}

// ===== tensor-core flash attention: bf16 hi/lo K/V streamed via cp.async ====
#define ASTR 72
#define KVSTG (4 * 64 * ASTR)
#define ATT_SMEM_BYTES (2 * KVSTG * 2)        // 73728 B

__global__ __launch_bounds__(256, 1) void attn_tc_kernel(
    const uint16_t* __restrict__ Qhi_g, const uint16_t* __restrict__ Qlo_g,
    const uint16_t* __restrict__ Khi_g, const uint16_t* __restrict__ Klo_g,
    const uint16_t* __restrict__ Vhi_g, const uint16_t* __restrict__ Vlo_g,
    float* __restrict__ O)
{
    extern __shared__ __align__(16) uint16_t asmm[];
    const int tid = threadIdx.x, lane = tid & 31, w = tid >> 5;
    const int nh = blockIdx.y;
    const int n = nh >> 4, h = nh & 15;
    const int q0blk = blockIdx.x * 128;

    const uint32_t s0 = (uint32_t)__cvta_generic_to_shared(asmm);
    const size_t nhbase = (size_t)nh * SEQ * HDIM;

    {
        #pragma unroll
        for (int i = 0; i < 8; i++) {
            int idx = i * 256 + tid;
            int t = idx >> 10, r = (idx >> 3) & 127, c = (idx & 7) * 8;
            const uint16_t* src = (t ? Qlo_g : Qhi_g)
                + nhbase + (size_t)(q0blk + r) * HDIM + c;
            uint32_t dst = s0 + (uint32_t)(KVSTG + t * 128 * ASTR + r * ASTR + c) * 2;
            CP_ASYNC16(dst, src);
        }
        CP_COMMIT;
    }
    const uint16_t* kvbase[4] = {Khi_g + nhbase, Klo_g + nhbase,
                                 Vhi_g + nhbase, Vlo_g + nhbase};
    {
        #pragma unroll
        for (int i = 0; i < 8; i++) {
            int idx = i * 256 + tid;
            int t = idx >> 9, r = (idx >> 3) & 63, c = (idx & 7) * 8;
            CP_ASYNC16(s0 + (uint32_t)(t * 64 * ASTR + r * ASTR + c) * 2,
                       kvbase[t] + (size_t)r * HDIM + c);
        }
        CP_COMMIT;
    }

    CP_WAIT1;
    __syncthreads();

    uint32_t aqh[4][4], aql[4][4];
    {
        int arow = w * 16 + (lane & 15);
        int aoff = ((lane >> 4) & 1) * 8;
        #pragma unroll
        for (int c = 0; c < 4; c++) {
            uint32_t off = (uint32_t)(KVSTG + arow * ASTR + c * 16 + aoff) * 2;
            LDSM_X4(aqh[c], s0 + off);
            LDSM_X4(aql[c], s0 + off + (uint32_t)(128 * ASTR) * 2);
        }
    }
    __syncthreads();

    float o[8][4];
    #pragma unroll
    for (int j = 0; j < 8; j++)
        #pragma unroll
        for (int c = 0; c < 4; c++) o[j][c] = 0.f;
    float m0 = -1e30f, m1 = -1e30f, l0 = 0.f, l1 = 0.f;

    const int kb_row = lane & 15;
    const int kb_col = ((lane >> 4) & 1) * 8;

    for (int kb = 0; kb < SEQ / 64; kb++) {
        const int cur = kb & 1;
        const bool more = (kb + 1 < SEQ / 64);

        if (more) {
            int nxt = cur ^ 1;
            size_t blk = (size_t)(kb + 1) * 64 * HDIM;
            #pragma unroll
            for (int i = 0; i < 8; i++) {
                int idx = i * 256 + tid;
                int t = idx >> 9, r = (idx >> 3) & 63, c = (idx & 7) * 8;
                CP_ASYNC16(s0 + (uint32_t)(nxt * KVSTG + t * 64 * ASTR + r * ASTR + c) * 2,
                           kvbase[t] + blk + (size_t)r * HDIM + c);
            }
            CP_COMMIT;
            CP_WAIT1;
        } else {
            CP_WAIT0;
        }
        __syncthreads();

        const uint32_t sKhi = s0 + (uint32_t)(cur * KVSTG) * 2;
        const uint32_t sKlo = sKhi + (uint32_t)(64 * ASTR) * 2;
        const uint32_t sVhi = sKhi + (uint32_t)(2 * 64 * ASTR) * 2;
        const uint32_t sVlo = sKhi + (uint32_t)(3 * 64 * ASTR) * 2;

        float s[8][4];
        #pragma unroll
        for (int j = 0; j < 8; j++)
            #pragma unroll
            for (int c = 0; c < 4; c++) s[j][c] = 0.f;

        #pragma unroll
        for (int c = 0; c < 4; c++) {
            #pragma unroll
            for (int j2 = 0; j2 < 4; j2++) {
                uint32_t kh[4], kl[4];
                uint32_t off = (uint32_t)((j2 * 16 + kb_row) * ASTR + c * 16 + kb_col) * 2;
                LDSM_X4(kh, sKhi + off);
                LDSM_X4(kl, sKlo + off);
                MMA_BF16(s[2*j2],   aqh[c], kh[0], kh[2]);
                MMA_BF16(s[2*j2],   aqh[c], kl[0], kl[2]);
                MMA_BF16(s[2*j2],   aql[c], kh[0], kh[2]);
                MMA_BF16(s[2*j2+1], aqh[c], kh[1], kh[3]);
                MMA_BF16(s[2*j2+1], aqh[c], kl[1], kl[3]);
                MMA_BF16(s[2*j2+1], aql[c], kh[1], kh[3]);
            }
        }

        float mx0 = -1e30f, mx1 = -1e30f;
        #pragma unroll
        for (int j = 0; j < 8; j++) {
            mx0 = fmaxf(mx0, fmaxf(s[j][0], s[j][1]));
            mx1 = fmaxf(mx1, fmaxf(s[j][2], s[j][3]));
        }
        mx0 = fmaxf(mx0, __shfl_xor_sync(0xffffffffu, mx0, 1));
        mx0 = fmaxf(mx0, __shfl_xor_sync(0xffffffffu, mx0, 2));
        mx1 = fmaxf(mx1, __shfl_xor_sync(0xffffffffu, mx1, 1));
        mx1 = fmaxf(mx1, __shfl_xor_sync(0xffffffffu, mx1, 2));
        float mn0 = fmaxf(m0, mx0), mn1 = fmaxf(m1, mx1);
        float corr0 = __expf(m0 - mn0), corr1 = __expf(m1 - mn1);
        m0 = mn0; m1 = mn1;

        float sum0 = 0.f, sum1 = 0.f;
        #pragma unroll
        for (int j = 0; j < 8; j++) {
            s[j][0] = __expf(s[j][0] - mn0); sum0 += s[j][0];
            s[j][1] = __expf(s[j][1] - mn0); sum0 += s[j][1];
            s[j][2] = __expf(s[j][2] - mn1); sum1 += s[j][2];
            s[j][3] = __expf(s[j][3] - mn1); sum1 += s[j][3];
        }
        sum0 += __shfl_xor_sync(0xffffffffu, sum0, 1);
        sum0 += __shfl_xor_sync(0xffffffffu, sum0, 2);
        sum1 += __shfl_xor_sync(0xffffffffu, sum1, 1);
        sum1 += __shfl_xor_sync(0xffffffffu, sum1, 2);
        l0 = l0 * corr0 + sum0;
        l1 = l1 * corr1 + sum1;

        #pragma unroll
        for (int j = 0; j < 8; j++) {
            o[j][0] *= corr0; o[j][1] *= corr0;
            o[j][2] *= corr1; o[j][3] *= corr1;
        }

        #pragma unroll
        for (int c = 0; c < 4; c++) {
            uint32_t ph[4], pl[4];
            split2(s[2*c][0],   s[2*c][1],   ph[0], pl[0]);
            split2(s[2*c][2],   s[2*c][3],   ph[1], pl[1]);
            split2(s[2*c+1][0], s[2*c+1][1], ph[2], pl[2]);
            split2(s[2*c+1][2], s[2*c+1][3], ph[3], pl[3]);
            #pragma unroll
            for (int j2 = 0; j2 < 4; j2++) {
                uint32_t vh[4], vl[4];
                uint32_t off = (uint32_t)((c * 16 + kb_row) * ASTR + j2 * 16 + kb_col) * 2;
                LDSM_X4_T(vh, sVhi + off);
                LDSM_X4_T(vl, sVlo + off);
                MMA_BF16(o[2*j2],   ph, vh[0], vh[1]);
                MMA_BF16(o[2*j2],   ph, vl[0], vl[1]);
                MMA_BF16(o[2*j2],   pl, vh[0], vh[1]);
                MMA_BF16(o[2*j2+1], ph, vh[2], vh[3]);
                MMA_BF16(o[2*j2+1], ph, vl[2], vl[3]);
                MMA_BF16(o[2*j2+1], pl, vh[2], vh[3]);
            }
        }
        __syncthreads();
    }

    float inv0 = 1.f / l0, inv1 = 1.f / l1;
    int qrow = q0blk + w * 16 + (lane >> 2);
    float* Ob0 = O + ((size_t)(n * SEQ) + qrow) * EMBED + h * 64 + (lane & 3) * 2;
    float* Ob1 = Ob0 + (size_t)8 * EMBED;
    #pragma unroll
    for (int j = 0; j < 8; j++) {
        *(float2*)&Ob0[j * 8] = make_float2(o[j][0] * inv0, o[j][1] * inv0);
        *(float2*)&Ob1[j * 8] = make_float2(o[j][2] * inv1, o[j][3] * inv1);
    }
}

// ==== tensor-core GEMM: A fp32 LDG+cvt fp16, B single fp16 (cp.async) =======
// 1 mma per tile: C = f16(A) @ f16(B) with fp32 accumulate.
#define GSTRIDE_A 40
#define GSTRIDE_B 136
#define ABUF (128 * GSTRIDE_A)
#define BBUF (32 * GSTRIDE_B)
#define GEMM_SMEM_BYTES ((2 * ABUF + 2 * BBUF) * 2)   // 37888

__global__ __launch_bounds__(256) void gemm_tc_f16(
    const float* __restrict__ A,
    const uint16_t* __restrict__ BHg,
    const float* __restrict__ bias, float* __restrict__ C,
    int M, int N, int K, int relu)
{
    extern __shared__ __align__(16) uint16_t dsm[];
    const int tid  = threadIdx.x;
    const int lane = tid & 31;
    const int wid  = tid >> 5;
    const int wm   = wid & 3;
    const int wn   = wid >> 2;
    const int bm   = blockIdx.y * 128;
    const int bn   = blockIdx.x * 128;

    const int ar  = tid >> 3, ac4 = (tid & 7) * 4;
    const int br  = tid >> 4, bc8 = (tid & 15) * 8;

    float4 pa[4];
    const int nk = K >> 5;
    const uint32_t s0 = (uint32_t)__cvta_generic_to_shared(dsm);

    {
        uint32_t dhi = s0 + (uint32_t)(2 * ABUF + br * GSTRIDE_B + bc8) * 2;
        #pragma unroll
        for (int i = 0; i < 2; i++)
            CP_ASYNC16(dhi + i * 16 * GSTRIDE_B * 2, &BHg[(size_t)(br + i * 16) * N + bn + bc8]);
        CP_COMMIT;
        #pragma unroll
        for (int i = 0; i < 4; i++)
            pa[i] = *(const float4*)&A[(size_t)(bm + ar + i * 32) * K + ac4];
        #pragma unroll
        for (int i = 0; i < 4; i++)
            f16_store4(dsm, (ar + i * 32) * GSTRIDE_A + ac4, pa[i]);
        CP_WAIT0;
    }
    __syncthreads();

    float acc[2][8][4];
    #pragma unroll
    for (int m = 0; m < 2; m++)
        #pragma unroll
        for (int n = 0; n < 8; n++)
            #pragma unroll
            for (int c = 0; c < 4; c++) acc[m][n][c] = 0.f;

    const int a_row = wm * 32 + (lane & 15);
    const int a_koff = ((lane >> 4) & 1) * 8;
    const int b_krow = (lane & 15);
    const int b_coff = wn * 64 + ((lane >> 4) & 1) * 8;

    for (int kb = 0; kb < nk; kb++) {
        const int cur = kb & 1, nxt = cur ^ 1;
        const bool more = (kb + 1 < nk);

        if (more) {
            int k0 = (kb + 1) * 32;
            uint32_t dhi = s0 + (uint32_t)(2 * ABUF + nxt * BBUF + br * GSTRIDE_B + bc8) * 2;
            #pragma unroll
            for (int i = 0; i < 2; i++)
                CP_ASYNC16(dhi + i * 16 * GSTRIDE_B * 2, &BHg[(size_t)(k0 + br + i * 16) * N + bn + bc8]);
            CP_COMMIT;
            #pragma unroll
            for (int i = 0; i < 4; i++)
                pa[i] = *(const float4*)&A[(size_t)(bm + ar + i * 32) * K + k0 + ac4];
        }

        const uint32_t bA   = s0 + (uint32_t)(cur * ABUF) * 2;
        const uint32_t bBhi = s0 + (uint32_t)(2 * ABUF + cur * BBUF) * 2;

        #pragma unroll
        for (int ks = 0; ks < 32; ks += 16) {
            uint32_t ah[2][4], bh[4][4];
            #pragma unroll
            for (int m = 0; m < 2; m++) {
                uint32_t off = ((a_row + m * 16) * GSTRIDE_A + ks + a_koff) * 2;
                LDSM_X4(ah[m], bA + off);
            }
            #pragma unroll
            for (int j = 0; j < 4; j++) {
                uint32_t off = ((ks + b_krow) * GSTRIDE_B + b_coff + j * 16) * 2;
                LDSM_X4_T(bh[j], bBhi + off);
            }
            #pragma unroll
            for (int m = 0; m < 2; m++)
                #pragma unroll
                for (int j = 0; j < 4; j++)
                    #pragma unroll
                    for (int t = 0; t < 2; t++) {
                        int n = j * 2 + t;
                        MMA_F16(acc[m][n], ah[m], bh[j][2*t], bh[j][2*t+1]);
                    }
        }

        if (more) {
            uint16_t* Ah = dsm + nxt * ABUF;
            #pragma unroll
            for (int i = 0; i < 4; i++)
                f16_store4(Ah, (ar + i * 32) * GSTRIDE_A + ac4, pa[i]);
            CP_WAIT0;
            __syncthreads();
        }
    }

    #pragma unroll
    for (int m = 0; m < 2; m++) {
        int row0 = bm + wm * 32 + m * 16 + (lane >> 2);
        #pragma unroll
        for (int n = 0; n < 8; n++) {
            int col = bn + wn * 64 + n * 8 + (lane & 3) * 2;
            float bx = bias[col], by = bias[col + 1];
            float2 v0 = make_float2(acc[m][n][0] + bx, acc[m][n][1] + by);
            float2 v1 = make_float2(acc[m][n][2] + bx, acc[m][n][3] + by);
            if (relu) {
                v0.x = fmaxf(v0.x, 0.f); v0.y = fmaxf(v0.y, 0.f);
                v1.x = fmaxf(v1.x, 0.f); v1.y = fmaxf(v1.y, 0.f);
            }
            *(float2*)&C[(size_t)row0 * N + col]       = v0;
            *(float2*)&C[(size_t)(row0 + 8) * N + col] = v1;
        }
    }
}

// ---------------- LayerNorm(A + R) * g + b : one pass, reg-resident -------
__global__ __launch_bounds__(256) void ln_kernel(
    const float* __restrict__ A, const float* __restrict__ R,
    const float* __restrict__ g, const float* __restrict__ b,
    float* __restrict__ Out)
{
    const int token = blockIdx.x, tid = threadIdx.x;
    const int lane = tid & 31, wid = tid >> 5;
    __shared__ float rs[8], rq[8];

    const float4 a = ((const float4*)A)[(size_t)token * 256 + tid];
    const float4 r = ((const float4*)R)[(size_t)token * 256 + tid];
    float4 v = make_float4(a.x + r.x, a.y + r.y, a.z + r.z, a.w + r.w);

    float sum = v.x + v.y + v.z + v.w;
    float sq  = v.x * v.x + v.y * v.y + v.z * v.z + v.w * v.w;
    #pragma unroll
    for (int off = 16; off > 0; off >>= 1) {
        sum += __shfl_xor_sync(0xffffffffu, sum, off);
        sq  += __shfl_xor_sync(0xffffffffu, sq,  off);
    }
    if (lane == 0) { rs[wid] = sum; rq[wid] = sq; }
    __syncthreads();
    if (tid == 0) {
        float S = 0.f, Qs = 0.f;
        #pragma unroll
        for (int i = 0; i < 8; i++) { S += rs[i]; Qs += rq[i]; }
        rs[0] = S; rq[0] = Qs;
    }
    __syncthreads();
    const float mean = rs[0] * (1.f / EMBED);
    const float var  = rq[0] * (1.f / EMBED) - mean * mean;
    const float rstd = rsqrtf(var + 1e-5f);

    const float4 gv = ((const float4*)g)[tid];
    const float4 bv = ((const float4*)b)[tid];
    float4 o;
    o.x = (v.x - mean) * rstd * gv.x + bv.x;
    o.y = (v.y - mean) * rstd * gv.y + bv.y;
    o.z = (v.z - mean) * rstd * gv.z + bv.z;
    o.w = (v.w - mean) * rstd * gv.w + bv.w;
    ((float4*)Out)[(size_t)token * 256 + tid] = o;
}

// ---------------- launcher ----------------
extern "C" void kernel_launch(void* const* d_in, const int* in_sizes, int n_in,
                              void* d_out, int out_size)
{
    const float* x       = (const float*)d_in[0];
    const float* embed_W = (const float*)d_in[2];
    const float* embed_b = (const float*)d_in[3];
    const float* pe      = (const float*)d_in[4];
    const float* Wq      = (const float*)d_in[5];
    const float* Wk      = (const float*)d_in[6];
    const float* Wv      = (const float*)d_in[7];
    const float* Wo      = (const float*)d_in[8];
    const float* bo      = (const float*)d_in[9];
    const float* ln1_g   = (const float*)d_in[10];
    const float* ln1_b   = (const float*)d_in[11];
    const float* W1      = (const float*)d_in[12];
    const float* b1      = (const float*)d_in[13];
    const float* W2      = (const float*)d_in[14];
    const float* b2      = (const float*)d_in[15];
    const float* ln2_g   = (const float*)d_in[16];
    const float* ln2_b   = (const float*)d_in[17];

    static float *H = nullptr, *X1, *T, *O, *F;
    static uint16_t *Qhi, *Qlo, *Khi, *Klo, *Vhi, *Vlo;
    static uint16_t *WoH, *W1H, *W2H, *EWHi, *EWLo;
    if (!H) {
        cudaGetSymbolAddress((void**)&H,  g_H);
        cudaGetSymbolAddress((void**)&X1, g_X1);
        cudaGetSymbolAddress((void**)&T,  g_T);
        cudaGetSymbolAddress((void**)&O,  g_O);
        cudaGetSymbolAddress((void**)&F,  g_F);
        cudaGetSymbolAddress((void**)&Qhi, g_Qhi);
        cudaGetSymbolAddress((void**)&Qlo, g_Qlo);
        cudaGetSymbolAddress((void**)&Khi, g_Khi);
        cudaGetSymbolAddress((void**)&Klo, g_Klo);
        cudaGetSymbolAddress((void**)&Vhi, g_Vhi);
        cudaGetSymbolAddress((void**)&Vlo, g_Vlo);
        cudaGetSymbolAddress((void**)&WoH, g_WoH);
        cudaGetSymbolAddress((void**)&W1H, g_W1H);
        cudaGetSymbolAddress((void**)&W2H, g_W2H);
        cudaGetSymbolAddress((void**)&EWHi, g_EWHi);
        cudaGetSymbolAddress((void**)&EWLo, g_EWLo);
        cudaFuncSetAttribute(gemm_tc_f16,
            cudaFuncAttributeMaxDynamicSharedMemorySize, GEMM_SMEM_BYTES);
        cudaFuncSetAttribute(qkv_tc_kernel,
            cudaFuncAttributeMaxDynamicSharedMemorySize, QKV_SMEM_BYTES);
        cudaFuncSetAttribute(attn_tc_kernel,
            cudaFuncAttributeMaxDynamicSharedMemorySize, ATT_SMEM_BYTES);
        cudaFuncSetAttribute(embed_tc_kernel,
            cudaFuncAttributeMaxDynamicSharedMemorySize, EMB_SMEM_BYTES);
    }

    {
        int n4o = 3 * EMBED * EMBED / 4;
        int n4f = 3 * EMBED * FFN_DIM / 4;
        int n4e = 64 * EMBED / 4;
        wconv_f16_kernel<<<(n4o + 255) / 256, 256>>>(Wo, WoH, n4o);
        wconv_f16_kernel<<<(n4f + 255) / 256, 256>>>(W1, W1H, n4f);
        wconv_f16_kernel<<<(n4f + 255) / 256, 256>>>(W2, W2H, n4f);
        wsplit_bf16_kernel<<<(n4e + 255) / 256, 256>>>(embed_W, EWHi, EWLo, n4e);
    }

    embed_tc_kernel<<<dim3(EMBED / 128, TOKENS / 128), 256, EMB_SMEM_BYTES>>>(
        x, EWHi, EWLo, embed_b, pe, H);

    for (int l = 0; l < 3; l++) {
        qkv_tc_kernel<<<TOKENS / 8, 256, QKV_SMEM_BYTES>>>(H,
            Wq + (size_t)l * HDIM * HDIM,
            Wk + (size_t)l * HDIM * HDIM,
            Wv + (size_t)l * HDIM * HDIM,
            Qhi, Qlo, Khi, Klo, Vhi, Vlo);

        attn_tc_kernel<<<dim3(SEQ / 128, BATCH * HEADS), 256, ATT_SMEM_BYTES>>>(
            Qhi, Qlo, Khi, Klo, Vhi, Vlo, O);

        gemm_tc_f16<<<dim3(EMBED / 128, TOKENS / 128), 256, GEMM_SMEM_BYTES>>>(
            O, WoH + (size_t)l * EMBED * EMBED,
            bo + (size_t)l * EMBED, T, TOKENS, EMBED, EMBED, 0);

        ln_kernel<<<TOKENS, 256>>>(T, H,
            ln1_g + (size_t)l * EMBED, ln1_b + (size_t)l * EMBED, X1);

        gemm_tc_f16<<<dim3(FFN_DIM / 128, TOKENS / 128), 256, GEMM_SMEM_BYTES>>>(
            X1, W1H + (size_t)l * EMBED * FFN_DIM,
            b1 + (size_t)l * FFN_DIM, F, TOKENS, FFN_DIM, EMBED, 1);

        gemm_tc_f16<<<dim3(EMBED / 128, TOKENS / 128), 256, GEMM_SMEM_BYTES>>>(
            F, W2H + (size_t)l * FFN_DIM * EMBED,
            b2 + (size_t)l * EMBED, T, TOKENS, EMBED, FFN_DIM, 0);

        float* dst = (l == 2) ? (float*)d_out : H;
        ln_kernel<<<TOKENS, 256>>>(T, X1,
            ln2_g + (size_t)l * EMBED, ln2_b + (size_t)l * EMBED, dst);
    }
    (void)in_sizes; (void)n_in; (void)out_size;
}